// round 8
// baseline (speedup 1.0000x reference)
#include <cuda_runtime.h>
#include <cuda_fp16.h>
#include <math.h>
#include <stdint.h>

#define B_   512
#define T_   32
#define FIN  4096
#define L_   256
#define M_   (B_*T_)
#define KCONV (3*FIN)

#define OFF_FEAT   0
#define OFF_ASSIGN 4194304
#define OFF_SEG    4210688
#define OFF_OUT    4227072
#define OFF_AT     4228096

// -------- scratch (device globals) --------
__device__ __align__(16) __half g_xh[(size_t)M_ * FIN];      // x fp16
__device__ __align__(16) __half g_wt[(size_t)L_ * KCONV];    // conv weight fp16 [n][k]
__device__ __align__(16) __half g_bw[229376];                // aV|aU|cs0|cs1 fp16 [n][256]
__device__ __align__(16) __half g_fhi[(size_t)M_ * L_];
__device__ __align__(16) __half g_flo[(size_t)M_ * L_];
__device__ __align__(16) __half g_h0hi[(size_t)M_ * 256];
__device__ __align__(16) __half g_h0lo[(size_t)M_ * 256];
__device__ float g_preVU[(size_t)M_ * 512];                  // [m][0:256)=V, [256:512)=U
__device__ float g_Amat[M_];
__device__ float g_bag[B_ * L_];
__device__ float g_h1[(size_t)M_ * 128];

// ======================= helpers =======================
__device__ __forceinline__ void splith(float v, __half& h, __half& l) {
    h = __float2half(v);
    l = __float2half(v - __half2float(h));
}
__device__ __forceinline__ uint32_t smem_u32(const void* p) {
    uint32_t a;
    asm("{ .reg .u64 t; cvta.to.shared.u64 t, %1; cvt.u32.u64 %0, t; }" : "=r"(a) : "l"(p));
    return a;
}
__device__ __forceinline__ void cp16(uint32_t dst, const void* src, uint32_t sz) {
    asm volatile("cp.async.cg.shared.global [%0], [%1], 16, %2;"
                 :: "r"(dst), "l"(src), "r"(sz) : "memory");
}
__device__ __forceinline__ void ldm4(uint32_t* r, uint32_t addr) {
    asm volatile("ldmatrix.sync.aligned.m8n8.x4.shared.b16 {%0,%1,%2,%3}, [%4];"
                 : "=r"(r[0]), "=r"(r[1]), "=r"(r[2]), "=r"(r[3]) : "r"(addr));
}
__device__ __forceinline__ void mma16816(float* c, const uint32_t* a, const uint32_t* b) {
    asm volatile("mma.sync.aligned.m16n8k16.row.col.f32.f16.f16.f32 "
                 "{%0,%1,%2,%3}, {%4,%5,%6,%7}, {%8,%9}, {%0,%1,%2,%3};"
                 : "+f"(c[0]), "+f"(c[1]), "+f"(c[2]), "+f"(c[3])
                 : "r"(a[0]), "r"(a[1]), "r"(a[2]), "r"(a[3]), "r"(b[0]), "r"(b[1]));
}
__device__ __forceinline__ float tanh_fast(float x) {
    float r;
    asm("tanh.approx.f32 %0, %1;" : "=f"(r) : "f"(x));
    return r;
}

// ======================= convert / repack kernels =======================
__global__ void conv_x_k(const float4* __restrict__ x, __half2* __restrict__ o) {
    size_t i = (size_t)blockIdx.x * 256 + threadIdx.x;
    float4 v = x[i];
    __half2 a, b;
    a.x = __float2half(v.x); a.y = __float2half(v.y);
    b.x = __float2half(v.z); b.y = __float2half(v.w);
    o[2 * i] = a; o[2 * i + 1] = b;
}

__global__ void splitw_conv_k(const float* __restrict__ w, __half* __restrict__ o) {
    int idx = blockIdx.x * 256 + threadIdx.x;          // [n][k], k = tap*4096 + c
    int n = idx / KCONV;
    int k = idx - n * KCONV;
    int tap = k >> 12, c = k & 4095;
    o[idx] = __float2half(w[(size_t)n * KCONV + c * 3 + tap]);
}

__global__ void splitw_pair_k(const float* __restrict__ wa, const float* __restrict__ wb,
                              __half* __restrict__ o) {
    int idx = blockIdx.x * 256 + threadIdx.x;          // 131072 total
    const float* w = (idx < 65536) ? wa : wb;
    int li = idx & 65535;
    o[idx] = __float2half(w[li]);
}

__global__ void splitw_gen_k(const float* __restrict__ w, int srcStride, int total,
                             __half* __restrict__ o) {
    int idx = blockIdx.x * 256 + threadIdx.x;
    if (idx >= total) return;
    int n = idx >> 8, k = idx & 255;
    o[idx] = __float2half(w[(size_t)n * srcStride + k]);
}

// ======================= HMMA GEMM (mma.sync fp16) =======================
// D[m][n] = epi( sum_k A[m][k]*B[n][k] + bias )
// TP=1: A hi/lo fp16 pair, 2 passes.  TP=0: single fp16, 1 pass.
// EPI: 0=bias, write fp32 + fp16 hi/lo   (conv -> feature)
//      2=relu(bias + exCol[m]*exW[n*257]), write fp16 hi/lo  (seg layer0)
//      3=relu(bias), write fp32          (seg layer1)
//      4=dual bias (n<256: bias[n], else exCol[n-256]), write fp32  (fused aV|aU)
template<int CONV, int EPI, int TP>
__global__ void __launch_bounds__(256, 2) mm_gemm(
    const __half* __restrict__ Ahi, const __half* __restrict__ Alo, int ldA,
    const __half* __restrict__ Bw, int ldB,
    const float* __restrict__ bias, const float* __restrict__ exCol,
    const float* __restrict__ exW,
    float* __restrict__ Cf, __half* __restrict__ Chi, __half* __restrict__ Clo,
    int N, int K)
{
    constexpr uint32_t STG  = TP ? 49152u : 32768u;
    constexpr uint32_t BOFF = TP ? 32768u : 16384u;
    extern __shared__ __align__(128) char smem[];
    const int tid = threadIdx.x;
    const int m0 = blockIdx.y * 128;
    const int n0 = blockIdx.x * 128;
    const uint32_t sb = smem_u32(smem);
    const int NCH = K >> 6;

    const int lane = tid & 31, warp = tid >> 5;
    const int wm = (warp >> 2) * 64, wn = (warp & 3) * 32;
    const int rsel = lane & 15, ksel = lane >> 4;

    float acc[4][4][4];
#pragma unroll
    for (int i = 0; i < 4; i++)
#pragma unroll
        for (int j = 0; j < 4; j++)
#pragma unroll
            for (int u = 0; u < 4; u++) acc[i][j][u] = 0.f;

    auto issue_load = [&](int ch) {
        const int s = ch & 1;
        const int k0 = ch << 6;
        if (tid < 128) {
            const int row = tid;
            const __half *srcH, *srcL = nullptr;
            uint32_t sz = 16;
            if (CONV) {
                const int tap = k0 >> 12;
                const int coff = k0 & 4095;
                long sr = (long)m0 + row + tap - 1;
                const int tt = (row & 31) + tap - 1;
                if (tt < 0 || tt > 31) { sz = 0; sr = m0 + row; }
                srcH = Ahi + sr * ldA + coff;
                if (TP) srcL = Alo + sr * ldA + coff;
            } else {
                srcH = Ahi + (size_t)(m0 + row) * ldA + k0;
                if (TP) srcL = Alo + (size_t)(m0 + row) * ldA + k0;
            }
            const uint32_t d = sb + s * STG + row * 128;
            const int xm = row & 7;
#pragma unroll
            for (int c = 0; c < 8; c++) {
                const uint32_t cc = (uint32_t)((c ^ xm) << 4);
                cp16(d + cc, srcH + c * 8, sz);
                if (TP) cp16(d + 16384 + cc, srcL + c * 8, sz);
            }
        } else {
            const int row = tid - 128;
            const __half* srcB = Bw + (size_t)(n0 + row) * ldB + k0;
            const uint32_t d = sb + s * STG + BOFF + row * 128;
            const int xm = row & 7;
#pragma unroll
            for (int c = 0; c < 8; c++) {
                const uint32_t cc = (uint32_t)((c ^ xm) << 4);
                cp16(d + cc, srcB + c * 8, 16);
            }
        }
        asm volatile("cp.async.commit_group;" ::: "memory");
    };

    issue_load(0);
    for (int ch = 0; ch < NCH; ch++) {
        if (ch + 1 < NCH) issue_load(ch + 1);
        if (ch + 1 < NCH) asm volatile("cp.async.wait_group 1;" ::: "memory");
        else              asm volatile("cp.async.wait_group 0;" ::: "memory");
        __syncthreads();
        const uint32_t base = sb + (ch & 1) * STG;
#pragma unroll
        for (int ks = 0; ks < 4; ks++) {
            const int kc = ks * 2 + ksel;
            uint32_t ah[4][4], al[4][4];
#pragma unroll
            for (int im = 0; im < 4; im++) {
                const int row = wm + im * 16 + rsel;
                const uint32_t a = base + row * 128 + (uint32_t)(((kc ^ (row & 7))) << 4);
                ldm4(ah[im], a);
                if (TP) ldm4(al[im], a + 16384);
            }
            uint32_t bh[4][2];
#pragma unroll
            for (int j2 = 0; j2 < 2; j2++) {
                const int row = wn + j2 * 16 + rsel;
                const uint32_t a = base + BOFF + row * 128 + (uint32_t)(((kc ^ (row & 7))) << 4);
                uint32_t t[4];
                ldm4(t, a);
                bh[j2 * 2][0] = t[0]; bh[j2 * 2][1] = t[2];
                bh[j2 * 2 + 1][0] = t[1]; bh[j2 * 2 + 1][1] = t[3];
            }
#pragma unroll
            for (int im = 0; im < 4; im++)
#pragma unroll
                for (int jn = 0; jn < 4; jn++) {
                    mma16816(acc[im][jn], ah[im], bh[jn]);
                    if (TP) mma16816(acc[im][jn], al[im], bh[jn]);
                }
        }
        __syncthreads();
    }

    // ---- epilogue ----
    const int g = lane >> 2, t4 = lane & 3;
#pragma unroll
    for (int im = 0; im < 4; im++) {
#pragma unroll
        for (int jn = 0; jn < 4; jn++) {
            const int n = n0 + wn + jn * 8 + t4 * 2;
            float bv0, bv1;
            if (EPI == 4) {
                bv0 = (n < 256) ? bias[n] : exCol[n - 256];
                bv1 = (n + 1 < 256) ? bias[n + 1] : exCol[n + 1 - 256];
            } else {
                bv0 = bias[n]; bv1 = bias[n + 1];
            }
            float ew0 = 0.f, ew1 = 0.f;
            if (EPI == 2) { ew0 = exW[(size_t)n * 257]; ew1 = exW[(size_t)(n + 1) * 257]; }
#pragma unroll
            for (int h = 0; h < 2; h++) {
                const int m = m0 + wm + im * 16 + g + h * 8;
                float v0 = acc[im][jn][h * 2 + 0] + bv0;
                float v1 = acc[im][jn][h * 2 + 1] + bv1;
                if (EPI == 2) {
                    const float ec = exCol[m];
                    v0 += ec * ew0; v1 += ec * ew1;
                }
                if (EPI == 2 || EPI == 3) { v0 = fmaxf(v0, 0.f); v1 = fmaxf(v1, 0.f); }
                const size_t off = (size_t)m * N + n;
                if (EPI != 2)
                    *reinterpret_cast<float2*>(Cf + off) = make_float2(v0, v1);
                if (EPI == 0 || EPI == 2) {
                    __half h0, l0, h1, l1;
                    splith(v0, h0, l0); splith(v1, h1, l1);
                    __half2 ph, pl;
                    ph.x = h0; ph.y = h1; pl.x = l0; pl.y = l1;
                    *reinterpret_cast<__half2*>(Chi + off) = ph;
                    *reinterpret_cast<__half2*>(Clo + off) = pl;
                }
            }
        }
    }
}

// ======================= gated attention combine (approx math) =======================
__global__ void __launch_bounds__(256) gated_kernel(
    const float* __restrict__ pvu,
    const float* __restrict__ gw, const float* __restrict__ gb,
    float* __restrict__ Amat)
{
    int m = blockIdx.x * 8 + (threadIdx.x >> 5);
    int lane = threadIdx.x & 31;
    const float* row = pvu + (size_t)m * 512;
    float acc = 0.f;
#pragma unroll
    for (int i = 0; i < 8; i++) {
        int d = lane + i * 32;
        float v = tanh_fast(row[d]);
        float u = __fdividef(1.f, 1.f + __expf(-row[256 + d]));
        acc += v * u * gw[d];
    }
#pragma unroll
    for (int o = 16; o; o >>= 1) acc += __shfl_xor_sync(0xffffffffu, acc, o);
    if (lane == 0) Amat[m] = acc + gb[0];
}

// ======================= softmax over T + bag + At =======================
__global__ void __launch_bounds__(256) softbag_kernel(
    const float* __restrict__ Amat, const float* __restrict__ feat,
    float* __restrict__ bag, float* __restrict__ outAt)
{
    __shared__ float p[32];
    int b = blockIdx.x;
    int tid = threadIdx.x;
    if (tid < 32) {
        float v = Amat[b * 32 + tid];
        outAt[b * 32 + tid] = v;
        float mx = v;
#pragma unroll
        for (int o = 16; o; o >>= 1) mx = fmaxf(mx, __shfl_xor_sync(0xffffffffu, mx, o));
        float e = expf(v - mx);
        float s = e;
#pragma unroll
        for (int o = 16; o; o >>= 1) s += __shfl_xor_sync(0xffffffffu, s, o);
        p[tid] = e / s;
    }
    __syncthreads();
    float acc = 0.f;
#pragma unroll 8
    for (int t = 0; t < 32; t++) acc += p[t] * feat[(size_t)(b * 32 + t) * 256 + tid];
    bag[b * 256 + tid] = acc;
}

// ======================= bag classifier =======================
__global__ void __launch_bounds__(256) bagclf_kernel(
    const float* __restrict__ bag,
    const float* __restrict__ w0, const float* __restrict__ b0,
    const float* __restrict__ w1, const float* __restrict__ b1,
    const float* __restrict__ w2, const float* __restrict__ b2,
    const float* __restrict__ w3, const float* __restrict__ b3,
    float* __restrict__ outp)
{
    __shared__ float sb[8 * 256];
    __shared__ float sh[8 * 256];
    int base = blockIdx.x * 8;
    int tid = threadIdx.x;
#pragma unroll
    for (int i = 0; i < 8; i++) sb[tid + i * 256] = bag[(size_t)base * 256 + tid + i * 256];
    __syncthreads();
    {
        float acc[8] = {0, 0, 0, 0, 0, 0, 0, 0};
        const float* w = w0 + (size_t)tid * 256;
        for (int l = 0; l < 256; l++) {
            float wv = w[l];
#pragma unroll
            for (int r = 0; r < 8; r++) acc[r] += wv * sb[r * 256 + l];
        }
        float bb = b0[tid];
#pragma unroll
        for (int r = 0; r < 8; r++) sh[r * 256 + tid] = fmaxf(acc[r] + bb, 0.f);
    }
    __syncthreads();
    if (tid < 128) {
        float acc[8] = {0, 0, 0, 0, 0, 0, 0, 0};
        const float* w = w1 + (size_t)tid * 256;
        for (int l = 0; l < 256; l++) {
            float wv = w[l];
#pragma unroll
            for (int r = 0; r < 8; r++) acc[r] += wv * sh[r * 256 + l];
        }
        float bb = b1[tid];
#pragma unroll
        for (int r = 0; r < 8; r++) sb[r * 128 + tid] = fmaxf(acc[r] + bb, 0.f);
    }
    __syncthreads();
    if (tid < 32) {
        float acc[8] = {0, 0, 0, 0, 0, 0, 0, 0};
        const float* w = w2 + (size_t)tid * 128;
        for (int l = 0; l < 128; l++) {
            float wv = w[l];
#pragma unroll
            for (int r = 0; r < 8; r++) acc[r] += wv * sb[r * 128 + l];
        }
        float bb = b2[tid];
#pragma unroll
        for (int r = 0; r < 8; r++) sh[r * 32 + tid] = fmaxf(acc[r] + bb, 0.f);
    }
    __syncthreads();
    if (tid < 8) {
        float a = 0.f;
        for (int j = 0; j < 32; j++) a += w3[j] * sh[tid * 32 + j];
        float o1 = 1.f / (1.f + expf(-(a + b3[0])));
        outp[(size_t)(base + tid) * 2 + 0] = 0.5f * o1;
    }
}

// ======================= seg tail =======================
__global__ void __launch_bounds__(256) segtail_kernel(
    const float* __restrict__ h1,
    const float* __restrict__ w2, const float* __restrict__ b2,
    const float* __restrict__ w3, const float* __restrict__ b3,
    float* __restrict__ out_seg)
{
    __shared__ float sw2[128 * 32];
    __shared__ float sh1[8 * 128];
    int m0 = blockIdx.x * 8;
    int tid = threadIdx.x;
#pragma unroll
    for (int i = 0; i < 16; i++) {
        int idx = tid + i * 256;
        sw2[(idx & 127) * 32 + (idx >> 7)] = w2[idx];
    }
#pragma unroll
    for (int i = 0; i < 4; i++) {
        int idx = tid + i * 256;
        sh1[idx] = h1[(size_t)m0 * 128 + idx];
    }
    __syncthreads();
    int r = tid >> 5, j = tid & 31;
    float acc = b2[j];
#pragma unroll 8
    for (int l = 0; l < 128; l++) acc += sw2[l * 32 + j] * sh1[r * 128 + l];
    float h2 = fmaxf(acc, 0.f);
    float v = h2 * w3[j];
#pragma unroll
    for (int o = 16; o; o >>= 1) v += __shfl_xor_sync(0xffffffffu, v, o);
    if (j == 0) out_seg[m0 + r] = 1.f / (1.f + expf(-(v + b3[0])));
}

// ======================= per-sample 2-means (cosine, cycle-detecting) ==============
// warp-per-t similarity; exact early exit on fixed points AND period-2 cycles
// (masks provably alternate once mask_it == mask_{it-2}; final = parity of 99-it).
__global__ void __launch_bounds__(1024) kmeans_kernel(
    const float* __restrict__ feat, const float* __restrict__ seg,
    float* __restrict__ out_assign, float* __restrict__ out_pair)
{
    __shared__ float sf[32 * 256];
    __shared__ float sc[2 * 256];
    __shared__ float sdiff[256];
    __shared__ float sinv[2];
    __shared__ int sassign[32];
    __shared__ unsigned smask;
    int b = blockIdx.x;
    int tid = threadIdx.x;
    int lane = tid & 31, w = tid >> 5;

    // load features (float4), then init centers from rows 0 and 16
    {
        const float4* src = reinterpret_cast<const float4*>(feat + (size_t)b * 8192);
        float4* dst = reinterpret_cast<float4*>(sf);
        dst[tid] = src[tid];
        dst[tid + 1024] = src[tid + 1024];
    }
    __syncthreads();
    if (tid < 256) {
        sc[tid] = sf[tid];
        sc[256 + tid] = sf[4096 + tid];
    }
    __syncthreads();

    unsigned prev1 = 0, prev2 = 0;
    unsigned final_mask = 0;
    for (int it = 0; it < 100; it++) {
        // center inverse norms (warps 0,1)
        if (w < 2) {
            float s = 0.f;
#pragma unroll
            for (int i = 0; i < 8; i++) {
                float v = sc[w * 256 + lane + i * 32];
                s += v * v;
            }
#pragma unroll
            for (int o = 16; o; o >>= 1) s += __shfl_xor_sync(0xffffffffu, s, o);
            if (lane == 0) sinv[w] = 1.f / (sqrtf(s) + 1e-8f);
        }
        __syncthreads();
        if (tid < 256) sdiff[tid] = sc[256 + tid] * sinv[1] - sc[tid] * sinv[0];
        __syncthreads();
        // warp w handles t = w: sign test f_t · diff > 0
        {
            float s = 0.f;
#pragma unroll
            for (int i = 0; i < 8; i++)
                s += sf[w * 256 + lane + i * 32] * sdiff[lane + i * 32];
#pragma unroll
            for (int o = 16; o; o >>= 1) s += __shfl_xor_sync(0xffffffffu, s, o);
            if (lane == 0) sassign[w] = (s > 0.f) ? 1 : 0;
        }
        __syncthreads();
        if (w == 0) {
            unsigned mk = __ballot_sync(0xffffffffu, sassign[lane] != 0);
            if (lane == 0) smask = mk;
        }
        __syncthreads();
        unsigned mask = smask;
        if (it >= 1 && mask == prev1) { final_mask = mask; break; }       // fixed point
        if (it >= 2 && mask == prev2) {                                   // period-2 cycle
            final_mask = (((99 - it) & 1) == 0) ? mask : prev1;
            break;
        }
        prev2 = prev1; prev1 = mask; final_mask = mask;
        if (it == 99) break;
        // center update (threads 0-255, one per (cluster,dim) column pair)
        if (tid < 256) {
            int cnt1 = __popc(mask);
            int cnt0 = 32 - cnt1;
            float a0 = 0.f, a1 = 0.f;
#pragma unroll
            for (int t = 0; t < 32; t++) {
                float fv = sf[t * 256 + tid];
                if ((mask >> t) & 1) a1 += fv; else a0 += fv;
            }
            if (cnt0 > 0) sc[tid] = a0 / (float)cnt0;
            if (cnt1 > 0) sc[256 + tid] = a1 / (float)cnt1;
        }
        __syncthreads();
    }

    if (tid < 32) {
        int bit = (final_mask >> tid) & 1;
        out_assign[b * 32 + tid] = (float)bit;
        float s = seg[b * 32 + tid];
        float v0 = bit ? 0.f : s;
        float v1 = bit ? s : 0.f;
#pragma unroll
        for (int o = 16; o; o >>= 1) {
            v0 += __shfl_xor_sync(0xffffffffu, v0, o);
            v1 += __shfl_xor_sync(0xffffffffu, v1, o);
        }
        int cnt1 = __popc(final_mask);
        int cnt0 = 32 - cnt1;
        float m0 = (cnt0 > 0) ? v0 / (float)cnt0 : -INFINITY;
        float m1 = (cnt1 > 0) ? v1 / (float)cnt1 : -INFINITY;
        if (tid == 0) out_pair[(size_t)b * 2 + 1] = 0.5f * fmaxf(m0, m1);
    }
}

// ======================= launch =======================
extern "C" void kernel_launch(void* const* d_in, const int* in_sizes, int n_in,
                              void* d_out, int out_size)
{
    const float* x      = (const float*)d_in[0];
    const float* tsn_w  = (const float*)d_in[1];
    const float* tsn_b  = (const float*)d_in[2];
    const float* aV_w   = (const float*)d_in[3];
    const float* aV_b   = (const float*)d_in[4];
    const float* aU_w   = (const float*)d_in[5];
    const float* aU_b   = (const float*)d_in[6];
    const float* gate_w = (const float*)d_in[7];
    const float* gate_b = (const float*)d_in[8];
    const float* cb_w0 = (const float*)d_in[9],  *cb_b0 = (const float*)d_in[10];
    const float* cb_w1 = (const float*)d_in[11], *cb_b1 = (const float*)d_in[12];
    const float* cb_w2 = (const float*)d_in[13], *cb_b2 = (const float*)d_in[14];
    const float* cb_w3 = (const float*)d_in[15], *cb_b3 = (const float*)d_in[16];
    const float* cs_w0 = (const float*)d_in[17], *cs_b0 = (const float*)d_in[18];
    const float* cs_w1 = (const float*)d_in[19], *cs_b1 = (const float*)d_in[20];
    const float* cs_w2 = (const float*)d_in[21], *cs_b2 = (const float*)d_in[22];
    const float* cs_w3 = (const float*)d_in[23], *cs_b3 = (const float*)d_in[24];

    float* out = (float*)d_out;
    float* feat    = out + OFF_FEAT;
    float* oAssign = out + OFF_ASSIGN;
    float* oSeg    = out + OFF_SEG;
    float* oOut    = out + OFF_OUT;
    float* oAt     = out + OFF_AT;

    __half *xh, *wt, *bw, *fhi, *flo, *h0hi, *h0lo;
    float *preVU, *Amat, *bag, *h1;
    cudaGetSymbolAddress((void**)&xh, g_xh);
    cudaGetSymbolAddress((void**)&wt, g_wt);     cudaGetSymbolAddress((void**)&bw, g_bw);
    cudaGetSymbolAddress((void**)&fhi, g_fhi);   cudaGetSymbolAddress((void**)&flo, g_flo);
    cudaGetSymbolAddress((void**)&h0hi, g_h0hi); cudaGetSymbolAddress((void**)&h0lo, g_h0lo);
    cudaGetSymbolAddress((void**)&preVU, g_preVU);
    cudaGetSymbolAddress((void**)&Amat, g_Amat); cudaGetSymbolAddress((void**)&bag, g_bag);
    cudaGetSymbolAddress((void**)&h1, g_h1);

    const int SMB1 = 2 * 32768;
    const int SMB2 = 2 * 49152;
    cudaFuncSetAttribute(mm_gemm<1, 0, 0>, cudaFuncAttributeMaxDynamicSharedMemorySize, SMB1);
    cudaFuncSetAttribute(mm_gemm<0, 4, 1>, cudaFuncAttributeMaxDynamicSharedMemorySize, SMB2);
    cudaFuncSetAttribute(mm_gemm<0, 2, 1>, cudaFuncAttributeMaxDynamicSharedMemorySize, SMB2);
    cudaFuncSetAttribute(mm_gemm<0, 3, 1>, cudaFuncAttributeMaxDynamicSharedMemorySize, SMB2);

    // my launches #1-#4 (1 hidden harness launch precedes; ncu -s 5 profiles my #5)
    conv_x_k<<<65536, 256>>>((const float4*)x, (__half2*)xh);
    splitw_conv_k<<<(L_ * KCONV) / 256, 256>>>(tsn_w, wt);
    splitw_pair_k<<<512, 256>>>(aV_w, aU_w, bw);
    splitw_gen_k<<<256, 256>>>(cs_w0, 257, 65536, bw + 131072);

    // #5: conv-as-GEMM (single fp16 pass) -> feature fp32 + fhi/flo  [PROFILED]
    mm_gemm<1, 0, 0><<<dim3(2, 128), 256, SMB1>>>(xh, nullptr, FIN, wt, KCONV,
                                                  tsn_b, nullptr, nullptr,
                                                  feat, fhi, flo, 256, KCONV);

    splitw_gen_k<<<128, 256>>>(cs_w1, 256, 32768, bw + 196608);

    // fused aV|aU projection (N=512, dual bias) -> preVU
    mm_gemm<0, 4, 1><<<dim3(4, 128), 256, SMB2>>>(fhi, flo, 256, bw, 256,
                                                  aV_b, aU_b, nullptr,
                                                  preVU, nullptr, nullptr, 512, 256);
    // gated combine + softmax/bag + bag classifier
    gated_kernel<<<M_ / 8, 256>>>(preVU, gate_w, gate_b, Amat);
    softbag_kernel<<<B_, 256>>>(Amat, feat, bag, oAt);
    bagclf_kernel<<<B_ / 8, 256>>>(bag, cb_w0, cb_b0, cb_w1, cb_b1,
                                   cb_w2, cb_b2, cb_w3, cb_b3, oOut);
    // seg classifier
    mm_gemm<0, 2, 1><<<dim3(2, 128), 256, SMB2>>>(fhi, flo, 256, bw + 131072, 256,
                                                  cs_b0, Amat, cs_w0 + 256,
                                                  nullptr, h0hi, h0lo, 256, 256);
    mm_gemm<0, 3, 1><<<dim3(1, 128), 256, SMB2>>>(h0hi, h0lo, 256, bw + 196608, 256,
                                                  cs_b1, nullptr, nullptr,
                                                  h1, nullptr, nullptr, 128, 256);
    segtail_kernel<<<M_ / 8, 256>>>(h1, cs_w2, cs_b2, cs_w3, cs_b3, oSeg);
    // 2-means -> assigns + output[:,1]
    kmeans_kernel<<<B_, 1024>>>(feat, oSeg, oAssign, oOut);
}

// round 9
// speedup vs baseline: 1.0267x; 1.0267x over previous
#include <cuda_runtime.h>
#include <cuda_fp16.h>
#include <math.h>
#include <stdint.h>

#define B_   512
#define T_   32
#define FIN  4096
#define L_   256
#define M_   (B_*T_)
#define KCONV (3*FIN)

#define OFF_FEAT   0
#define OFF_ASSIGN 4194304
#define OFF_SEG    4210688
#define OFF_OUT    4227072
#define OFF_AT     4228096

// -------- scratch (device globals) --------
__device__ __align__(16) __half g_xh[(size_t)M_ * FIN];      // x fp16
__device__ __align__(16) __half g_wt[(size_t)L_ * KCONV];    // conv weight fp16 [n][k]
__device__ __align__(16) __half g_bw[229376];                // aVU(interleaved ok)|cs0|cs1 fp16
__device__ __align__(16) __half g_fhi[(size_t)M_ * L_];
__device__ __align__(16) __half g_flo[(size_t)M_ * L_];
__device__ __align__(16) __half g_h0hi[(size_t)M_ * 256];
__device__ __align__(16) __half g_h0lo[(size_t)M_ * 256];
__device__ float g_preVU[(size_t)M_ * 512];
__device__ float g_Amat[M_];
__device__ float g_bag[B_ * L_];
__device__ float g_h1[(size_t)M_ * 128];
__device__ int   g_kmask[B_];

// ======================= helpers =======================
__device__ __forceinline__ void splith(float v, __half& h, __half& l) {
    h = __float2half(v);
    l = __float2half(v - __half2float(h));
}
__device__ __forceinline__ uint32_t smem_u32(const void* p) {
    uint32_t a;
    asm("{ .reg .u64 t; cvta.to.shared.u64 t, %1; cvt.u32.u64 %0, t; }" : "=r"(a) : "l"(p));
    return a;
}
__device__ __forceinline__ void cp16(uint32_t dst, const void* src, uint32_t sz) {
    asm volatile("cp.async.cg.shared.global [%0], [%1], 16, %2;"
                 :: "r"(dst), "l"(src), "r"(sz) : "memory");
}
__device__ __forceinline__ void ldm4(uint32_t* r, uint32_t addr) {
    asm volatile("ldmatrix.sync.aligned.m8n8.x4.shared.b16 {%0,%1,%2,%3}, [%4];"
                 : "=r"(r[0]), "=r"(r[1]), "=r"(r[2]), "=r"(r[3]) : "r"(addr));
}
__device__ __forceinline__ void mma16816(float* c, const uint32_t* a, const uint32_t* b) {
    asm volatile("mma.sync.aligned.m16n8k16.row.col.f32.f16.f16.f32 "
                 "{%0,%1,%2,%3}, {%4,%5,%6,%7}, {%8,%9}, {%0,%1,%2,%3};"
                 : "+f"(c[0]), "+f"(c[1]), "+f"(c[2]), "+f"(c[3])
                 : "r"(a[0]), "r"(a[1]), "r"(a[2]), "r"(a[3]), "r"(b[0]), "r"(b[1]));
}
__device__ __forceinline__ float tanh_fast(float x) {
    float r;
    asm("tanh.approx.f32 %0, %1;" : "=f"(r) : "f"(x));
    return r;
}

// ======================= convert / repack kernels =======================
__global__ void conv_x_k(const float4* __restrict__ x, __half2* __restrict__ o) {
    size_t i = (size_t)blockIdx.x * 256 + threadIdx.x;
    float4 v = x[i];
    __half2 a, b;
    a.x = __float2half(v.x); a.y = __float2half(v.y);
    b.x = __float2half(v.z); b.y = __float2half(v.w);
    o[2 * i] = a; o[2 * i + 1] = b;
}

__global__ void splitw_conv_k(const float* __restrict__ w, __half* __restrict__ o) {
    int idx = blockIdx.x * 256 + threadIdx.x;          // [n][k], k = tap*4096 + c
    int n = idx / KCONV;
    int k = idx - n * KCONV;
    int tap = k >> 12, c = k & 4095;
    o[idx] = __float2half(w[(size_t)n * KCONV + c * 3 + tap]);
}

__global__ void splitw_pair_k(const float* __restrict__ wa, const float* __restrict__ wb,
                              __half* __restrict__ o) {
    int idx = blockIdx.x * 256 + threadIdx.x;          // 131072 total
    const float* w = (idx < 65536) ? wa : wb;
    int li = idx & 65535;
    o[idx] = __float2half(w[li]);
}

__global__ void splitw_gen_k(const float* __restrict__ w, int srcStride, int total,
                             __half* __restrict__ o) {
    int idx = blockIdx.x * 256 + threadIdx.x;
    if (idx >= total) return;
    int n = idx >> 8, k = idx & 255;
    o[idx] = __float2half(w[(size_t)n * srcStride + k]);
}

// ======================= HMMA GEMM (mma.sync fp16) =======================
// D[m][n] = epi( sum_k A[m][k]*B[n][k] + bias )
// TP=1: A hi/lo fp16 pair, 2 passes.  TP=0: single fp16, 1 pass.
// EPI: 0=bias, write fp32 + fp16 hi/lo   (conv -> feature)
//      2=relu(bias + exCol[m]*exW[n*257]), write fp16 hi/lo  (seg layer0)
//      3=relu(bias), write fp32          (seg layer1)
//      4=dual bias (n<256: bias[n], else exCol[n-256]), write fp32  (fused aV|aU)
template<int CONV, int EPI, int TP>
__global__ void __launch_bounds__(256, 2) mm_gemm(
    const __half* __restrict__ Ahi, const __half* __restrict__ Alo, int ldA,
    const __half* __restrict__ Bw, int ldB,
    const float* __restrict__ bias, const float* __restrict__ exCol,
    const float* __restrict__ exW,
    float* __restrict__ Cf, __half* __restrict__ Chi, __half* __restrict__ Clo,
    int N, int K)
{
    constexpr uint32_t STG  = TP ? 49152u : 32768u;
    constexpr uint32_t BOFF = TP ? 32768u : 16384u;
    extern __shared__ __align__(128) char smem[];
    const int tid = threadIdx.x;
    const int m0 = blockIdx.y * 128;
    const int n0 = blockIdx.x * 128;
    const uint32_t sb = smem_u32(smem);
    const int NCH = K >> 6;

    const int lane = tid & 31, warp = tid >> 5;
    const int wm = (warp >> 2) * 64, wn = (warp & 3) * 32;
    const int rsel = lane & 15, ksel = lane >> 4;

    float acc[4][4][4];
#pragma unroll
    for (int i = 0; i < 4; i++)
#pragma unroll
        for (int j = 0; j < 4; j++)
#pragma unroll
            for (int u = 0; u < 4; u++) acc[i][j][u] = 0.f;

    auto issue_load = [&](int ch) {
        const int s = ch & 1;
        const int k0 = ch << 6;
        if (tid < 128) {
            const int row = tid;
            const __half *srcH, *srcL = nullptr;
            uint32_t sz = 16;
            if (CONV) {
                const int tap = k0 >> 12;
                const int coff = k0 & 4095;
                long sr = (long)m0 + row + tap - 1;
                const int tt = (row & 31) + tap - 1;
                if (tt < 0 || tt > 31) { sz = 0; sr = m0 + row; }
                srcH = Ahi + sr * ldA + coff;
                if (TP) srcL = Alo + sr * ldA + coff;
            } else {
                srcH = Ahi + (size_t)(m0 + row) * ldA + k0;
                if (TP) srcL = Alo + (size_t)(m0 + row) * ldA + k0;
            }
            const uint32_t d = sb + s * STG + row * 128;
            const int xm = row & 7;
#pragma unroll
            for (int c = 0; c < 8; c++) {
                const uint32_t cc = (uint32_t)((c ^ xm) << 4);
                cp16(d + cc, srcH + c * 8, sz);
                if (TP) cp16(d + 16384 + cc, srcL + c * 8, sz);
            }
        } else {
            const int row = tid - 128;
            const __half* srcB = Bw + (size_t)(n0 + row) * ldB + k0;
            const uint32_t d = sb + s * STG + BOFF + row * 128;
            const int xm = row & 7;
#pragma unroll
            for (int c = 0; c < 8; c++) {
                const uint32_t cc = (uint32_t)((c ^ xm) << 4);
                cp16(d + cc, srcB + c * 8, 16);
            }
        }
        asm volatile("cp.async.commit_group;" ::: "memory");
    };

    issue_load(0);
    for (int ch = 0; ch < NCH; ch++) {
        if (ch + 1 < NCH) issue_load(ch + 1);
        if (ch + 1 < NCH) asm volatile("cp.async.wait_group 1;" ::: "memory");
        else              asm volatile("cp.async.wait_group 0;" ::: "memory");
        __syncthreads();
        const uint32_t base = sb + (ch & 1) * STG;
#pragma unroll
        for (int ks = 0; ks < 4; ks++) {
            const int kc = ks * 2 + ksel;
            uint32_t ah[4][4], al[4][4];
#pragma unroll
            for (int im = 0; im < 4; im++) {
                const int row = wm + im * 16 + rsel;
                const uint32_t a = base + row * 128 + (uint32_t)(((kc ^ (row & 7))) << 4);
                ldm4(ah[im], a);
                if (TP) ldm4(al[im], a + 16384);
            }
            uint32_t bh[4][2];
#pragma unroll
            for (int j2 = 0; j2 < 2; j2++) {
                const int row = wn + j2 * 16 + rsel;
                const uint32_t a = base + BOFF + row * 128 + (uint32_t)(((kc ^ (row & 7))) << 4);
                uint32_t t[4];
                ldm4(t, a);
                bh[j2 * 2][0] = t[0]; bh[j2 * 2][1] = t[2];
                bh[j2 * 2 + 1][0] = t[1]; bh[j2 * 2 + 1][1] = t[3];
            }
#pragma unroll
            for (int im = 0; im < 4; im++)
#pragma unroll
                for (int jn = 0; jn < 4; jn++) {
                    mma16816(acc[im][jn], ah[im], bh[jn]);
                    if (TP) mma16816(acc[im][jn], al[im], bh[jn]);
                }
        }
        __syncthreads();
    }

    // ---- epilogue ----
    const int g = lane >> 2, t4 = lane & 3;
#pragma unroll
    for (int im = 0; im < 4; im++) {
#pragma unroll
        for (int jn = 0; jn < 4; jn++) {
            const int n = n0 + wn + jn * 8 + t4 * 2;
            float bv0, bv1;
            if (EPI == 4) {
                bv0 = (n < 256) ? bias[n] : exCol[n - 256];
                bv1 = (n + 1 < 256) ? bias[n + 1] : exCol[n + 1 - 256];
            } else {
                bv0 = bias[n]; bv1 = bias[n + 1];
            }
            float ew0 = 0.f, ew1 = 0.f;
            if (EPI == 2) { ew0 = exW[(size_t)n * 257]; ew1 = exW[(size_t)(n + 1) * 257]; }
#pragma unroll
            for (int h = 0; h < 2; h++) {
                const int m = m0 + wm + im * 16 + g + h * 8;
                float v0 = acc[im][jn][h * 2 + 0] + bv0;
                float v1 = acc[im][jn][h * 2 + 1] + bv1;
                if (EPI == 2) {
                    const float ec = exCol[m];
                    v0 += ec * ew0; v1 += ec * ew1;
                }
                if (EPI == 2 || EPI == 3) { v0 = fmaxf(v0, 0.f); v1 = fmaxf(v1, 0.f); }
                const size_t off = (size_t)m * N + n;
                if (EPI != 2)
                    *reinterpret_cast<float2*>(Cf + off) = make_float2(v0, v1);
                if (EPI == 0 || EPI == 2) {
                    __half h0, l0, h1, l1;
                    splith(v0, h0, l0); splith(v1, h1, l1);
                    __half2 ph, pl;
                    ph.x = h0; ph.y = h1; pl.x = l0; pl.y = l1;
                    *reinterpret_cast<__half2*>(Chi + off) = ph;
                    *reinterpret_cast<__half2*>(Clo + off) = pl;
                }
            }
        }
    }
}

// ======================= gated attention combine (approx math) =======================
__global__ void __launch_bounds__(256) gated_kernel(
    const float* __restrict__ pvu,
    const float* __restrict__ gw, const float* __restrict__ gb,
    float* __restrict__ Amat)
{
    int m = blockIdx.x * 8 + (threadIdx.x >> 5);
    int lane = threadIdx.x & 31;
    const float* row = pvu + (size_t)m * 512;
    float acc = 0.f;
#pragma unroll
    for (int i = 0; i < 8; i++) {
        int d = lane + i * 32;
        float v = tanh_fast(row[d]);
        float u = __fdividef(1.f, 1.f + __expf(-row[256 + d]));
        acc += v * u * gw[d];
    }
#pragma unroll
    for (int o = 16; o; o >>= 1) acc += __shfl_xor_sync(0xffffffffu, acc, o);
    if (lane == 0) Amat[m] = acc + gb[0];
}

// ======================= softmax over T + bag + At =======================
__global__ void __launch_bounds__(256) softbag_kernel(
    const float* __restrict__ Amat, const float* __restrict__ feat,
    float* __restrict__ bag, float* __restrict__ outAt)
{
    __shared__ float p[32];
    int b = blockIdx.x;
    int tid = threadIdx.x;
    if (tid < 32) {
        float v = Amat[b * 32 + tid];
        outAt[b * 32 + tid] = v;
        float mx = v;
#pragma unroll
        for (int o = 16; o; o >>= 1) mx = fmaxf(mx, __shfl_xor_sync(0xffffffffu, mx, o));
        float e = expf(v - mx);
        float s = e;
#pragma unroll
        for (int o = 16; o; o >>= 1) s += __shfl_xor_sync(0xffffffffu, s, o);
        p[tid] = e / s;
    }
    __syncthreads();
    float acc = 0.f;
#pragma unroll 8
    for (int t = 0; t < 32; t++) acc += p[t] * feat[(size_t)(b * 32 + t) * 256 + tid];
    bag[b * 256 + tid] = acc;
}

// ======================= bag classifier =======================
__global__ void __launch_bounds__(256) bagclf_kernel(
    const float* __restrict__ bag,
    const float* __restrict__ w0, const float* __restrict__ b0,
    const float* __restrict__ w1, const float* __restrict__ b1,
    const float* __restrict__ w2, const float* __restrict__ b2,
    const float* __restrict__ w3, const float* __restrict__ b3,
    float* __restrict__ outp)
{
    __shared__ float sb[8 * 256];
    __shared__ float sh[8 * 256];
    int base = blockIdx.x * 8;
    int tid = threadIdx.x;
#pragma unroll
    for (int i = 0; i < 8; i++) sb[tid + i * 256] = bag[(size_t)base * 256 + tid + i * 256];
    __syncthreads();
    {
        float acc[8] = {0, 0, 0, 0, 0, 0, 0, 0};
        const float* w = w0 + (size_t)tid * 256;
        for (int l = 0; l < 256; l++) {
            float wv = w[l];
#pragma unroll
            for (int r = 0; r < 8; r++) acc[r] += wv * sb[r * 256 + l];
        }
        float bb = b0[tid];
#pragma unroll
        for (int r = 0; r < 8; r++) sh[r * 256 + tid] = fmaxf(acc[r] + bb, 0.f);
    }
    __syncthreads();
    if (tid < 128) {
        float acc[8] = {0, 0, 0, 0, 0, 0, 0, 0};
        const float* w = w1 + (size_t)tid * 256;
        for (int l = 0; l < 256; l++) {
            float wv = w[l];
#pragma unroll
            for (int r = 0; r < 8; r++) acc[r] += wv * sh[r * 256 + l];
        }
        float bb = b1[tid];
#pragma unroll
        for (int r = 0; r < 8; r++) sb[r * 128 + tid] = fmaxf(acc[r] + bb, 0.f);
    }
    __syncthreads();
    if (tid < 32) {
        float acc[8] = {0, 0, 0, 0, 0, 0, 0, 0};
        const float* w = w2 + (size_t)tid * 128;
        for (int l = 0; l < 128; l++) {
            float wv = w[l];
#pragma unroll
            for (int r = 0; r < 8; r++) acc[r] += wv * sb[r * 128 + l];
        }
        float bb = b2[tid];
#pragma unroll
        for (int r = 0; r < 8; r++) sh[r * 32 + tid] = fmaxf(acc[r] + bb, 0.f);
    }
    __syncthreads();
    if (tid < 8) {
        float a = 0.f;
        for (int j = 0; j < 32; j++) a += w3[j] * sh[tid * 32 + j];
        float o1 = 1.f / (1.f + expf(-(a + b3[0])));
        outp[(size_t)(base + tid) * 2 + 0] = 0.5f * o1;
    }
}

// ======================= seg tail =======================
__global__ void __launch_bounds__(256) segtail_kernel(
    const float* __restrict__ h1,
    const float* __restrict__ w2, const float* __restrict__ b2,
    const float* __restrict__ w3, const float* __restrict__ b3,
    float* __restrict__ out_seg)
{
    __shared__ float sw2[128 * 32];
    __shared__ float sh1[8 * 128];
    int m0 = blockIdx.x * 8;
    int tid = threadIdx.x;
#pragma unroll
    for (int i = 0; i < 16; i++) {
        int idx = tid + i * 256;
        sw2[(idx & 127) * 32 + (idx >> 7)] = w2[idx];
    }
#pragma unroll
    for (int i = 0; i < 4; i++) {
        int idx = tid + i * 256;
        sh1[idx] = h1[(size_t)m0 * 128 + idx];
    }
    __syncthreads();
    int r = tid >> 5, j = tid & 31;
    float acc = b2[j];
#pragma unroll 8
    for (int l = 0; l < 128; l++) acc += sw2[l * 32 + j] * sh1[r * 128 + l];
    float h2 = fmaxf(acc, 0.f);
    float v = h2 * w3[j];
#pragma unroll
    for (int o = 16; o; o >>= 1) v += __shfl_xor_sync(0xffffffffu, v, o);
    if (j == 0) out_seg[m0 + r] = 1.f / (1.f + expf(-(v + b3[0])));
}

// ======================= per-sample 2-means (assign only; overlappable) ============
__global__ void __launch_bounds__(1024) kmeans_assign_k(
    const float* __restrict__ feat,
    float* __restrict__ out_assign, int* __restrict__ out_mask)
{
    __shared__ float sf[32 * 256];
    __shared__ float sc[2 * 256];
    __shared__ float sdiff[256];
    __shared__ float sinv[2];
    __shared__ int sassign[32];
    __shared__ unsigned smask;
    int b = blockIdx.x;
    int tid = threadIdx.x;
    int lane = tid & 31, w = tid >> 5;

    {
        const float4* src = reinterpret_cast<const float4*>(feat + (size_t)b * 8192);
        float4* dst = reinterpret_cast<float4*>(sf);
        dst[tid] = src[tid];
        dst[tid + 1024] = src[tid + 1024];
    }
    __syncthreads();
    if (tid < 256) {
        sc[tid] = sf[tid];
        sc[256 + tid] = sf[4096 + tid];
    }
    __syncthreads();

    unsigned prev1 = 0, prev2 = 0;
    unsigned final_mask = 0;
    for (int it = 0; it < 100; it++) {
        if (w < 2) {
            float s = 0.f;
#pragma unroll
            for (int i = 0; i < 8; i++) {
                float v = sc[w * 256 + lane + i * 32];
                s += v * v;
            }
#pragma unroll
            for (int o = 16; o; o >>= 1) s += __shfl_xor_sync(0xffffffffu, s, o);
            if (lane == 0) sinv[w] = 1.f / (sqrtf(s) + 1e-8f);
        }
        __syncthreads();
        if (tid < 256) sdiff[tid] = sc[256 + tid] * sinv[1] - sc[tid] * sinv[0];
        __syncthreads();
        {
            float s = 0.f;
#pragma unroll
            for (int i = 0; i < 8; i++)
                s += sf[w * 256 + lane + i * 32] * sdiff[lane + i * 32];
#pragma unroll
            for (int o = 16; o; o >>= 1) s += __shfl_xor_sync(0xffffffffu, s, o);
            if (lane == 0) sassign[w] = (s > 0.f) ? 1 : 0;
        }
        __syncthreads();
        if (w == 0) {
            unsigned mk = __ballot_sync(0xffffffffu, sassign[lane] != 0);
            if (lane == 0) smask = mk;
        }
        __syncthreads();
        unsigned mask = smask;
        if (it >= 1 && mask == prev1) { final_mask = mask; break; }
        if (it >= 2 && mask == prev2) {
            final_mask = (((99 - it) & 1) == 0) ? mask : prev1;
            break;
        }
        prev2 = prev1; prev1 = mask; final_mask = mask;
        if (it == 99) break;
        if (tid < 256) {
            int cnt1 = __popc(mask);
            int cnt0 = 32 - cnt1;
            float a0 = 0.f, a1 = 0.f;
#pragma unroll
            for (int t = 0; t < 32; t++) {
                float fv = sf[t * 256 + tid];
                if ((mask >> t) & 1) a1 += fv; else a0 += fv;
            }
            if (cnt0 > 0) sc[tid] = a0 / (float)cnt0;
            if (cnt1 > 0) sc[256 + tid] = a1 / (float)cnt1;
        }
        __syncthreads();
    }

    if (tid < 32) {
        out_assign[b * 32 + tid] = (float)((final_mask >> tid) & 1);
        if (tid == 0) out_mask[b] = (int)final_mask;
    }
}

// ======================= output2 join (mask + seg -> output[:,1]) =================
__global__ void __launch_bounds__(256) out2_k(
    const int* __restrict__ mask_arr, const float* __restrict__ seg,
    float* __restrict__ outp)
{
    int b = blockIdx.x * 8 + (threadIdx.x >> 5);
    int lane = threadIdx.x & 31;
    unsigned mask = (unsigned)mask_arr[b];
    float s = seg[b * 32 + lane];
    int bit = (mask >> lane) & 1;
    float v0 = bit ? 0.f : s;
    float v1 = bit ? s : 0.f;
#pragma unroll
    for (int o = 16; o; o >>= 1) {
        v0 += __shfl_xor_sync(0xffffffffu, v0, o);
        v1 += __shfl_xor_sync(0xffffffffu, v1, o);
    }
    if (lane == 0) {
        int cnt1 = __popc(mask);
        int cnt0 = 32 - cnt1;
        float m0 = (cnt0 > 0) ? v0 / (float)cnt0 : -INFINITY;
        float m1 = (cnt1 > 0) ? v1 / (float)cnt1 : -INFINITY;
        outp[(size_t)b * 2 + 1] = 0.5f * fmaxf(m0, m1);
    }
}

// ======================= launch =======================
extern "C" void kernel_launch(void* const* d_in, const int* in_sizes, int n_in,
                              void* d_out, int out_size)
{
    const float* x      = (const float*)d_in[0];
    const float* tsn_w  = (const float*)d_in[1];
    const float* tsn_b  = (const float*)d_in[2];
    const float* aV_w   = (const float*)d_in[3];
    const float* aV_b   = (const float*)d_in[4];
    const float* aU_w   = (const float*)d_in[5];
    const float* aU_b   = (const float*)d_in[6];
    const float* gate_w = (const float*)d_in[7];
    const float* gate_b = (const float*)d_in[8];
    const float* cb_w0 = (const float*)d_in[9],  *cb_b0 = (const float*)d_in[10];
    const float* cb_w1 = (const float*)d_in[11], *cb_b1 = (const float*)d_in[12];
    const float* cb_w2 = (const float*)d_in[13], *cb_b2 = (const float*)d_in[14];
    const float* cb_w3 = (const float*)d_in[15], *cb_b3 = (const float*)d_in[16];
    const float* cs_w0 = (const float*)d_in[17], *cs_b0 = (const float*)d_in[18];
    const float* cs_w1 = (const float*)d_in[19], *cs_b1 = (const float*)d_in[20];
    const float* cs_w2 = (const float*)d_in[21], *cs_b2 = (const float*)d_in[22];
    const float* cs_w3 = (const float*)d_in[23], *cs_b3 = (const float*)d_in[24];

    float* out = (float*)d_out;
    float* feat    = out + OFF_FEAT;
    float* oAssign = out + OFF_ASSIGN;
    float* oSeg    = out + OFF_SEG;
    float* oOut    = out + OFF_OUT;
    float* oAt     = out + OFF_AT;

    __half *xh, *wt, *bw, *fhi, *flo, *h0hi, *h0lo;
    float *preVU, *Amat, *bag, *h1;
    int* kmask;
    cudaGetSymbolAddress((void**)&xh, g_xh);
    cudaGetSymbolAddress((void**)&wt, g_wt);     cudaGetSymbolAddress((void**)&bw, g_bw);
    cudaGetSymbolAddress((void**)&fhi, g_fhi);   cudaGetSymbolAddress((void**)&flo, g_flo);
    cudaGetSymbolAddress((void**)&h0hi, g_h0hi); cudaGetSymbolAddress((void**)&h0lo, g_h0lo);
    cudaGetSymbolAddress((void**)&preVU, g_preVU);
    cudaGetSymbolAddress((void**)&Amat, g_Amat); cudaGetSymbolAddress((void**)&bag, g_bag);
    cudaGetSymbolAddress((void**)&h1, g_h1);
    cudaGetSymbolAddress((void**)&kmask, g_kmask);

    // side streams/events (host resources only; created once, graph-capture-forkable)
    static cudaStream_t s1 = nullptr, s2 = nullptr;
    static cudaEvent_t evRoot, evW, evFeat, evKm, evA, evSeg;
    if (s1 == nullptr) {
        cudaStreamCreateWithFlags(&s1, cudaStreamNonBlocking);
        cudaStreamCreateWithFlags(&s2, cudaStreamNonBlocking);
        cudaEventCreateWithFlags(&evRoot, cudaEventDisableTiming);
        cudaEventCreateWithFlags(&evW,    cudaEventDisableTiming);
        cudaEventCreateWithFlags(&evFeat, cudaEventDisableTiming);
        cudaEventCreateWithFlags(&evKm,   cudaEventDisableTiming);
        cudaEventCreateWithFlags(&evA,    cudaEventDisableTiming);
        cudaEventCreateWithFlags(&evSeg,  cudaEventDisableTiming);
    }

    const int SMB1 = 2 * 32768;
    const int SMB2 = 2 * 49152;
    cudaFuncSetAttribute(mm_gemm<1, 0, 0>, cudaFuncAttributeMaxDynamicSharedMemorySize, SMB1);
    cudaFuncSetAttribute(mm_gemm<0, 4, 1>, cudaFuncAttributeMaxDynamicSharedMemorySize, SMB2);
    cudaFuncSetAttribute(mm_gemm<0, 2, 1>, cudaFuncAttributeMaxDynamicSharedMemorySize, SMB2);
    cudaFuncSetAttribute(mm_gemm<0, 3, 1>, cudaFuncAttributeMaxDynamicSharedMemorySize, SMB2);

    // fork point for weight-split side stream
    cudaEventRecord(evRoot, 0);
    cudaStreamWaitEvent(s1, evRoot, 0);

    // #1, #2 on main stream (conv inputs)
    conv_x_k<<<65536, 256>>>((const float4*)x, (__half2*)xh);
    splitw_conv_k<<<(L_ * KCONV) / 256, 256>>>(tsn_w, wt);
    // #3 on s1 (overlaps with conv prep/GEMM)
    splitw_pair_k<<<512, 256, 0, s1>>>(aV_w, aU_w, bw);

    // #4: conv-as-GEMM -> feature fp32 + fhi/flo  [PROFILED: overall launch #6]
    mm_gemm<1, 0, 0><<<dim3(2, 128), 256, SMB1>>>(xh, nullptr, FIN, wt, KCONV,
                                                  tsn_b, nullptr, nullptr,
                                                  feat, fhi, flo, 256, KCONV);
    cudaEventRecord(evFeat, 0);

    // remaining weight splits on s1
    splitw_gen_k<<<256, 256, 0, s1>>>(cs_w0, 257, 65536, bw + 131072);
    splitw_gen_k<<<128, 256, 0, s1>>>(cs_w1, 256, 32768, bw + 196608);
    cudaEventRecord(evW, s1);

    // kmeans on s2, overlapping the whole attention/classifier chain
    cudaStreamWaitEvent(s2, evFeat, 0);
    kmeans_assign_k<<<B_, 1024, 0, s2>>>(feat, oAssign, kmask);
    cudaEventRecord(evKm, s2);

    // main chain: fused aV|aU -> gated
    cudaStreamWaitEvent(0, evW, 0);
    mm_gemm<0, 4, 1><<<dim3(4, 128), 256, SMB2>>>(fhi, flo, 256, bw, 256,
                                                  aV_b, aU_b, nullptr,
                                                  preVU, nullptr, nullptr, 512, 256);
    gated_kernel<<<M_ / 8, 256>>>(preVU, gate_w, gate_b, Amat);
    cudaEventRecord(evA, 0);

    // seg chain forked to s1 (parallel with softbag/bagclf)
    cudaStreamWaitEvent(s1, evA, 0);
    mm_gemm<0, 2, 1><<<dim3(2, 128), 256, SMB2, s1>>>(fhi, flo, 256, bw + 131072, 256,
                                                      cs_b0, Amat, cs_w0 + 256,
                                                      nullptr, h0hi, h0lo, 256, 256);
    mm_gemm<0, 3, 1><<<dim3(1, 128), 256, SMB2, s1>>>(h0hi, h0lo, 256, bw + 196608, 256,
                                                      cs_b1, nullptr, nullptr,
                                                      h1, nullptr, nullptr, 128, 256);
    segtail_kernel<<<M_ / 8, 256, 0, s1>>>(h1, cs_w2, cs_b2, cs_w3, cs_b3, oSeg);
    cudaEventRecord(evSeg, s1);

    // bag chain on main stream
    softbag_kernel<<<B_, 256>>>(Amat, feat, bag, oAt);
    bagclf_kernel<<<B_ / 8, 256>>>(bag, cb_w0, cb_b0, cb_w1, cb_b1,
                                   cb_w2, cb_b2, cb_w3, cb_b3, oOut);

    // join: output2 needs seg + kmeans masks
    cudaStreamWaitEvent(0, evSeg, 0);
    cudaStreamWaitEvent(0, evKm, 0);
    out2_k<<<B_ / 8, 256>>>(kmask, oSeg, oOut);
}

// round 10
// speedup vs baseline: 1.0535x; 1.0261x over previous
#include <cuda_runtime.h>
#include <cuda_fp16.h>
#include <math.h>
#include <stdint.h>

#define B_   512
#define T_   32
#define FIN  4096
#define L_   256
#define M_   (B_*T_)
#define KCONV (3*FIN)

#define OFF_FEAT   0
#define OFF_ASSIGN 4194304
#define OFF_SEG    4210688
#define OFF_OUT    4227072
#define OFF_AT     4228096

// -------- scratch (device globals) --------
__device__ __align__(16) __half g_xh[(size_t)M_ * FIN];      // x fp16
__device__ __align__(16) __half g_wt[(size_t)L_ * KCONV];    // conv weight fp16 [n][k]
__device__ __align__(16) __half g_bw[229376];                // aVU|cs0|cs1 fp16
__device__ __align__(16) __half g_fhi[(size_t)M_ * L_];
__device__ __align__(16) __half g_flo[(size_t)M_ * L_];
__device__ __align__(16) __half g_h0hi[(size_t)M_ * 256];
__device__ __align__(16) __half g_h0lo[(size_t)M_ * 256];
__device__ float g_preVU[(size_t)M_ * 512];
__device__ float g_Amat[M_];
__device__ float g_bag[B_ * L_];
__device__ float g_h1[(size_t)M_ * 128];
__device__ int   g_kmask[B_];

// ======================= helpers =======================
__device__ __forceinline__ void splith(float v, __half& h, __half& l) {
    h = __float2half(v);
    l = __float2half(v - __half2float(h));
}
__device__ __forceinline__ uint32_t smem_u32(const void* p) {
    uint32_t a;
    asm("{ .reg .u64 t; cvta.to.shared.u64 t, %1; cvt.u32.u64 %0, t; }" : "=r"(a) : "l"(p));
    return a;
}
__device__ __forceinline__ void cp16(uint32_t dst, const void* src, uint32_t sz) {
    asm volatile("cp.async.cg.shared.global [%0], [%1], 16, %2;"
                 :: "r"(dst), "l"(src), "r"(sz) : "memory");
}
__device__ __forceinline__ void ldm4(uint32_t* r, uint32_t addr) {
    asm volatile("ldmatrix.sync.aligned.m8n8.x4.shared.b16 {%0,%1,%2,%3}, [%4];"
                 : "=r"(r[0]), "=r"(r[1]), "=r"(r[2]), "=r"(r[3]) : "r"(addr));
}
__device__ __forceinline__ void mma16816(float* c, const uint32_t* a, const uint32_t* b) {
    asm volatile("mma.sync.aligned.m16n8k16.row.col.f32.f16.f16.f32 "
                 "{%0,%1,%2,%3}, {%4,%5,%6,%7}, {%8,%9}, {%0,%1,%2,%3};"
                 : "+f"(c[0]), "+f"(c[1]), "+f"(c[2]), "+f"(c[3])
                 : "r"(a[0]), "r"(a[1]), "r"(a[2]), "r"(a[3]), "r"(b[0]), "r"(b[1]));
}
__device__ __forceinline__ float tanh_fast(float x) {
    float r;
    asm("tanh.approx.f32 %0, %1;" : "=f"(r) : "f"(x));
    return r;
}

// ======================= convert / repack kernels =======================
__global__ void conv_x_k(const float4* __restrict__ x, __half2* __restrict__ o) {
    size_t i = (size_t)blockIdx.x * 256 + threadIdx.x;
    float4 v = x[i];
    __half2 a, b;
    a.x = __float2half(v.x); a.y = __float2half(v.y);
    b.x = __float2half(v.z); b.y = __float2half(v.w);
    o[2 * i] = a; o[2 * i + 1] = b;
}

__global__ void splitw_conv_k(const float* __restrict__ w, __half* __restrict__ o) {
    int idx = blockIdx.x * 256 + threadIdx.x;          // [n][k], k = tap*4096 + c
    int n = idx / KCONV;
    int k = idx - n * KCONV;
    int tap = k >> 12, c = k & 4095;
    o[idx] = __float2half(w[(size_t)n * KCONV + c * 3 + tap]);
}

__global__ void splitw_pair_k(const float* __restrict__ wa, const float* __restrict__ wb,
                              __half* __restrict__ o) {
    int idx = blockIdx.x * 256 + threadIdx.x;          // 131072 total
    const float* w = (idx < 65536) ? wa : wb;
    int li = idx & 65535;
    o[idx] = __float2half(w[li]);
}

__global__ void splitw_gen_k(const float* __restrict__ w, int srcStride, int total,
                             __half* __restrict__ o) {
    int idx = blockIdx.x * 256 + threadIdx.x;
    if (idx >= total) return;
    int n = idx >> 8, k = idx & 255;
    o[idx] = __float2half(w[(size_t)n * srcStride + k]);
}

// ======================= HMMA GEMM (mma.sync fp16) =======================
// D[m][n] = epi( sum_k A[m][k]*B[n][k] + bias ),  m = m_base + blockIdx.y*128 + ...
// TP=1: A hi/lo fp16 pair, 2 passes.  TP=0: single fp16, 1 pass.
// S-stage cp.async ring, ONE __syncthreads per chunk:
//   wait_group -> barrier -> issue(ch+S-1) -> compute(ch)
// EPI: 0=bias, write fp32 + fp16 hi/lo   (conv -> feature)
//      2=relu(bias + exCol[m]*exW[n*257]), write fp16 hi/lo  (seg layer0)
//      3=relu(bias), write fp32          (seg layer1)
//      4=dual bias (n<256: bias[n], else exCol[n-256]), write fp32  (fused aV|aU)
template<int CONV, int EPI, int TP, int S>
__global__ void __launch_bounds__(256, 2) mm_gemm(
    const __half* __restrict__ Ahi, const __half* __restrict__ Alo, int ldA,
    const __half* __restrict__ Bw, int ldB,
    const float* __restrict__ bias, const float* __restrict__ exCol,
    const float* __restrict__ exW,
    float* __restrict__ Cf, __half* __restrict__ Chi, __half* __restrict__ Clo,
    int N, int K, int m_base)
{
    constexpr uint32_t STG  = TP ? 49152u : 32768u;
    constexpr uint32_t BOFF = TP ? 32768u : 16384u;
    extern __shared__ __align__(128) char smem[];
    const int tid = threadIdx.x;
    const int m0 = m_base + blockIdx.y * 128;
    const int n0 = blockIdx.x * 128;
    const uint32_t sb = smem_u32(smem);
    const int NCH = K >> 6;

    const int lane = tid & 31, warp = tid >> 5;
    const int wm = (warp >> 2) * 64, wn = (warp & 3) * 32;
    const int rsel = lane & 15, ksel = lane >> 4;

    float acc[4][4][4];
#pragma unroll
    for (int i = 0; i < 4; i++)
#pragma unroll
        for (int j = 0; j < 4; j++)
#pragma unroll
            for (int u = 0; u < 4; u++) acc[i][j][u] = 0.f;

    auto issue_load = [&](int ch) {
        const uint32_t slot = (uint32_t)(ch % S);
        const int k0 = ch << 6;
        if (tid < 128) {
            const int row = tid;
            const __half *srcH, *srcL = nullptr;
            uint32_t sz = 16;
            if (CONV) {
                const int tap = k0 >> 12;
                const int coff = k0 & 4095;
                long sr = (long)m0 + row + tap - 1;
                const int tt = (row & 31) + tap - 1;
                if (tt < 0 || tt > 31) { sz = 0; sr = m0 + row; }
                srcH = Ahi + sr * ldA + coff;
                if (TP) srcL = Alo + sr * ldA + coff;
            } else {
                srcH = Ahi + (size_t)(m0 + row) * ldA + k0;
                if (TP) srcL = Alo + (size_t)(m0 + row) * ldA + k0;
            }
            const uint32_t d = sb + slot * STG + row * 128;
            const int xm = row & 7;
#pragma unroll
            for (int c = 0; c < 8; c++) {
                const uint32_t cc = (uint32_t)((c ^ xm) << 4);
                cp16(d + cc, srcH + c * 8, sz);
                if (TP) cp16(d + 16384 + cc, srcL + c * 8, sz);
            }
        } else {
            const int row = tid - 128;
            const __half* srcB = Bw + (size_t)(n0 + row) * ldB + k0;
            const uint32_t d = sb + slot * STG + BOFF + row * 128;
            const int xm = row & 7;
#pragma unroll
            for (int c = 0; c < 8; c++) {
                const uint32_t cc = (uint32_t)((c ^ xm) << 4);
                cp16(d + cc, srcB + c * 8, 16);
            }
        }
        asm volatile("cp.async.commit_group;" ::: "memory");
    };

#pragma unroll
    for (int i = 0; i < S - 1; i++) issue_load(i);

    for (int ch = 0; ch < NCH; ch++) {
        // group ch must be complete; allowed pending = newest_committed - ch
        if (ch + S - 2 < NCH - 1)
            asm volatile("cp.async.wait_group %0;" :: "n"(S - 2) : "memory");
        else
            asm volatile("cp.async.wait_group 0;" ::: "memory");
        __syncthreads();
        if (ch + S - 1 < NCH) issue_load(ch + S - 1);

        const uint32_t base = sb + (uint32_t)(ch % S) * STG;
#pragma unroll
        for (int ks = 0; ks < 4; ks++) {
            const int kc = ks * 2 + ksel;
            uint32_t ah[4][4], al[4][4];
#pragma unroll
            for (int im = 0; im < 4; im++) {
                const int row = wm + im * 16 + rsel;
                const uint32_t a = base + row * 128 + (uint32_t)(((kc ^ (row & 7))) << 4);
                ldm4(ah[im], a);
                if (TP) ldm4(al[im], a + 16384);
            }
            uint32_t bh[4][2];
#pragma unroll
            for (int j2 = 0; j2 < 2; j2++) {
                const int row = wn + j2 * 16 + rsel;
                const uint32_t a = base + BOFF + row * 128 + (uint32_t)(((kc ^ (row & 7))) << 4);
                uint32_t t[4];
                ldm4(t, a);
                bh[j2 * 2][0] = t[0]; bh[j2 * 2][1] = t[2];
                bh[j2 * 2 + 1][0] = t[1]; bh[j2 * 2 + 1][1] = t[3];
            }
#pragma unroll
            for (int im = 0; im < 4; im++)
#pragma unroll
                for (int jn = 0; jn < 4; jn++) {
                    mma16816(acc[im][jn], ah[im], bh[jn]);
                    if (TP) mma16816(acc[im][jn], al[im], bh[jn]);
                }
        }
    }

    // ---- epilogue ----
    const int g = lane >> 2, t4 = lane & 3;
#pragma unroll
    for (int im = 0; im < 4; im++) {
#pragma unroll
        for (int jn = 0; jn < 4; jn++) {
            const int n = n0 + wn + jn * 8 + t4 * 2;
            float bv0, bv1;
            if (EPI == 4) {
                bv0 = (n < 256) ? bias[n] : exCol[n - 256];
                bv1 = (n + 1 < 256) ? bias[n + 1] : exCol[n + 1 - 256];
            } else {
                bv0 = bias[n]; bv1 = bias[n + 1];
            }
            float ew0 = 0.f, ew1 = 0.f;
            if (EPI == 2) { ew0 = exW[(size_t)n * 257]; ew1 = exW[(size_t)(n + 1) * 257]; }
#pragma unroll
            for (int h = 0; h < 2; h++) {
                const int m = m0 + wm + im * 16 + g + h * 8;
                float v0 = acc[im][jn][h * 2 + 0] + bv0;
                float v1 = acc[im][jn][h * 2 + 1] + bv1;
                if (EPI == 2) {
                    const float ec = exCol[m];
                    v0 += ec * ew0; v1 += ec * ew1;
                }
                if (EPI == 2 || EPI == 3) { v0 = fmaxf(v0, 0.f); v1 = fmaxf(v1, 0.f); }
                const size_t off = (size_t)m * N + n;
                if (EPI != 2)
                    *reinterpret_cast<float2*>(Cf + off) = make_float2(v0, v1);
                if (EPI == 0 || EPI == 2) {
                    __half h0, l0, h1, l1;
                    splith(v0, h0, l0); splith(v1, h1, l1);
                    __half2 ph, pl;
                    ph.x = h0; ph.y = h1; pl.x = l0; pl.y = l1;
                    *reinterpret_cast<__half2*>(Chi + off) = ph;
                    *reinterpret_cast<__half2*>(Clo + off) = pl;
                }
            }
        }
    }
}

// ======================= gated attention combine (approx math) =======================
__global__ void __launch_bounds__(256) gated_kernel(
    const float* __restrict__ pvu,
    const float* __restrict__ gw, const float* __restrict__ gb,
    float* __restrict__ Amat)
{
    int m = blockIdx.x * 8 + (threadIdx.x >> 5);
    int lane = threadIdx.x & 31;
    const float* row = pvu + (size_t)m * 512;
    float acc = 0.f;
#pragma unroll
    for (int i = 0; i < 8; i++) {
        int d = lane + i * 32;
        float v = tanh_fast(row[d]);
        float u = __fdividef(1.f, 1.f + __expf(-row[256 + d]));
        acc += v * u * gw[d];
    }
#pragma unroll
    for (int o = 16; o; o >>= 1) acc += __shfl_xor_sync(0xffffffffu, acc, o);
    if (lane == 0) Amat[m] = acc + gb[0];
}

// ======================= softmax over T + bag + At =======================
__global__ void __launch_bounds__(256) softbag_kernel(
    const float* __restrict__ Amat, const float* __restrict__ feat,
    float* __restrict__ bag, float* __restrict__ outAt)
{
    __shared__ float p[32];
    int b = blockIdx.x;
    int tid = threadIdx.x;
    if (tid < 32) {
        float v = Amat[b * 32 + tid];
        outAt[b * 32 + tid] = v;
        float mx = v;
#pragma unroll
        for (int o = 16; o; o >>= 1) mx = fmaxf(mx, __shfl_xor_sync(0xffffffffu, mx, o));
        float e = expf(v - mx);
        float s = e;
#pragma unroll
        for (int o = 16; o; o >>= 1) s += __shfl_xor_sync(0xffffffffu, s, o);
        p[tid] = e / s;
    }
    __syncthreads();
    float acc = 0.f;
#pragma unroll 8
    for (int t = 0; t < 32; t++) acc += p[t] * feat[(size_t)(b * 32 + t) * 256 + tid];
    bag[b * 256 + tid] = acc;
}

// ======================= bag classifier =======================
__global__ void __launch_bounds__(256) bagclf_kernel(
    const float* __restrict__ bag,
    const float* __restrict__ w0, const float* __restrict__ b0,
    const float* __restrict__ w1, const float* __restrict__ b1,
    const float* __restrict__ w2, const float* __restrict__ b2,
    const float* __restrict__ w3, const float* __restrict__ b3,
    float* __restrict__ outp)
{
    __shared__ float sb[8 * 256];
    __shared__ float sh[8 * 256];
    int base = blockIdx.x * 8;
    int tid = threadIdx.x;
#pragma unroll
    for (int i = 0; i < 8; i++) sb[tid + i * 256] = bag[(size_t)base * 256 + tid + i * 256];
    __syncthreads();
    {
        float acc[8] = {0, 0, 0, 0, 0, 0, 0, 0};
        const float* w = w0 + (size_t)tid * 256;
        for (int l = 0; l < 256; l++) {
            float wv = w[l];
#pragma unroll
            for (int r = 0; r < 8; r++) acc[r] += wv * sb[r * 256 + l];
        }
        float bb = b0[tid];
#pragma unroll
        for (int r = 0; r < 8; r++) sh[r * 256 + tid] = fmaxf(acc[r] + bb, 0.f);
    }
    __syncthreads();
    if (tid < 128) {
        float acc[8] = {0, 0, 0, 0, 0, 0, 0, 0};
        const float* w = w1 + (size_t)tid * 256;
        for (int l = 0; l < 256; l++) {
            float wv = w[l];
#pragma unroll
            for (int r = 0; r < 8; r++) acc[r] += wv * sh[r * 256 + l];
        }
        float bb = b1[tid];
#pragma unroll
        for (int r = 0; r < 8; r++) sb[r * 128 + tid] = fmaxf(acc[r] + bb, 0.f);
    }
    __syncthreads();
    if (tid < 32) {
        float acc[8] = {0, 0, 0, 0, 0, 0, 0, 0};
        const float* w = w2 + (size_t)tid * 128;
        for (int l = 0; l < 128; l++) {
            float wv = w[l];
#pragma unroll
            for (int r = 0; r < 8; r++) acc[r] += wv * sb[r * 128 + l];
        }
        float bb = b2[tid];
#pragma unroll
        for (int r = 0; r < 8; r++) sh[r * 32 + tid] = fmaxf(acc[r] + bb, 0.f);
    }
    __syncthreads();
    if (tid < 8) {
        float a = 0.f;
        for (int j = 0; j < 32; j++) a += w3[j] * sh[tid * 32 + j];
        float o1 = 1.f / (1.f + expf(-(a + b3[0])));
        outp[(size_t)(base + tid) * 2 + 0] = 0.5f * o1;
    }
}

// ======================= seg tail =======================
__global__ void __launch_bounds__(256) segtail_kernel(
    const float* __restrict__ h1,
    const float* __restrict__ w2, const float* __restrict__ b2,
    const float* __restrict__ w3, const float* __restrict__ b3,
    float* __restrict__ out_seg)
{
    __shared__ float sw2[128 * 32];
    __shared__ float sh1[8 * 128];
    int m0 = blockIdx.x * 8;
    int tid = threadIdx.x;
#pragma unroll
    for (int i = 0; i < 16; i++) {
        int idx = tid + i * 256;
        sw2[(idx & 127) * 32 + (idx >> 7)] = w2[idx];
    }
#pragma unroll
    for (int i = 0; i < 4; i++) {
        int idx = tid + i * 256;
        sh1[idx] = h1[(size_t)m0 * 128 + idx];
    }
    __syncthreads();
    int r = tid >> 5, j = tid & 31;
    float acc = b2[j];
#pragma unroll 8
    for (int l = 0; l < 128; l++) acc += sw2[l * 32 + j] * sh1[r * 128 + l];
    float h2 = fmaxf(acc, 0.f);
    float v = h2 * w3[j];
#pragma unroll
    for (int o = 16; o; o >>= 1) v += __shfl_xor_sync(0xffffffffu, v, o);
    if (j == 0) out_seg[m0 + r] = 1.f / (1.f + expf(-(v + b3[0])));
}

// ======================= per-sample 2-means (assign only; overlappable) ============
__global__ void __launch_bounds__(1024) kmeans_assign_k(
    const float* __restrict__ feat,
    float* __restrict__ out_assign, int* __restrict__ out_mask)
{
    __shared__ float sf[32 * 256];
    __shared__ float sc[2 * 256];
    __shared__ float sdiff[256];
    __shared__ float sinv[2];
    __shared__ int sassign[32];
    __shared__ unsigned smask;
    int b = blockIdx.x;
    int tid = threadIdx.x;
    int lane = tid & 31, w = tid >> 5;

    {
        const float4* src = reinterpret_cast<const float4*>(feat + (size_t)b * 8192);
        float4* dst = reinterpret_cast<float4*>(sf);
        dst[tid] = src[tid];
        dst[tid + 1024] = src[tid + 1024];
    }
    __syncthreads();
    if (tid < 256) {
        sc[tid] = sf[tid];
        sc[256 + tid] = sf[4096 + tid];
    }
    __syncthreads();

    unsigned prev1 = 0, prev2 = 0;
    unsigned final_mask = 0;
    for (int it = 0; it < 100; it++) {
        if (w < 2) {
            float s = 0.f;
#pragma unroll
            for (int i = 0; i < 8; i++) {
                float v = sc[w * 256 + lane + i * 32];
                s += v * v;
            }
#pragma unroll
            for (int o = 16; o; o >>= 1) s += __shfl_xor_sync(0xffffffffu, s, o);
            if (lane == 0) sinv[w] = 1.f / (sqrtf(s) + 1e-8f);
        }
        __syncthreads();
        if (tid < 256) sdiff[tid] = sc[256 + tid] * sinv[1] - sc[tid] * sinv[0];
        __syncthreads();
        {
            float s = 0.f;
#pragma unroll
            for (int i = 0; i < 8; i++)
                s += sf[w * 256 + lane + i * 32] * sdiff[lane + i * 32];
#pragma unroll
            for (int o = 16; o; o >>= 1) s += __shfl_xor_sync(0xffffffffu, s, o);
            if (lane == 0) sassign[w] = (s > 0.f) ? 1 : 0;
        }
        __syncthreads();
        if (w == 0) {
            unsigned mk = __ballot_sync(0xffffffffu, sassign[lane] != 0);
            if (lane == 0) smask = mk;
        }
        __syncthreads();
        unsigned mask = smask;
        if (it >= 1 && mask == prev1) { final_mask = mask; break; }
        if (it >= 2 && mask == prev2) {
            final_mask = (((99 - it) & 1) == 0) ? mask : prev1;
            break;
        }
        prev2 = prev1; prev1 = mask; final_mask = mask;
        if (it == 99) break;
        if (tid < 256) {
            int cnt1 = __popc(mask);
            int cnt0 = 32 - cnt1;
            float a0 = 0.f, a1 = 0.f;
#pragma unroll
            for (int t = 0; t < 32; t++) {
                float fv = sf[t * 256 + tid];
                if ((mask >> t) & 1) a1 += fv; else a0 += fv;
            }
            if (cnt0 > 0) sc[tid] = a0 / (float)cnt0;
            if (cnt1 > 0) sc[256 + tid] = a1 / (float)cnt1;
        }
        __syncthreads();
    }

    if (tid < 32) {
        out_assign[b * 32 + tid] = (float)((final_mask >> tid) & 1);
        if (tid == 0) out_mask[b] = (int)final_mask;
    }
}

// ======================= output2 join (mask + seg -> output[:,1]) =================
__global__ void __launch_bounds__(256) out2_k(
    const int* __restrict__ mask_arr, const float* __restrict__ seg,
    float* __restrict__ outp)
{
    int b = blockIdx.x * 8 + (threadIdx.x >> 5);
    int lane = threadIdx.x & 31;
    unsigned mask = (unsigned)mask_arr[b];
    float s = seg[b * 32 + lane];
    int bit = (mask >> lane) & 1;
    float v0 = bit ? 0.f : s;
    float v1 = bit ? s : 0.f;
#pragma unroll
    for (int o = 16; o; o >>= 1) {
        v0 += __shfl_xor_sync(0xffffffffu, v0, o);
        v1 += __shfl_xor_sync(0xffffffffu, v1, o);
    }
    if (lane == 0) {
        int cnt1 = __popc(mask);
        int cnt0 = 32 - cnt1;
        float m0 = (cnt0 > 0) ? v0 / (float)cnt0 : -INFINITY;
        float m1 = (cnt1 > 0) ? v1 / (float)cnt1 : -INFINITY;
        outp[(size_t)b * 2 + 1] = 0.5f * fmaxf(m0, m1);
    }
}

// ======================= launch =======================
extern "C" void kernel_launch(void* const* d_in, const int* in_sizes, int n_in,
                              void* d_out, int out_size)
{
    const float* x      = (const float*)d_in[0];
    const float* tsn_w  = (const float*)d_in[1];
    const float* tsn_b  = (const float*)d_in[2];
    const float* aV_w   = (const float*)d_in[3];
    const float* aV_b   = (const float*)d_in[4];
    const float* aU_w   = (const float*)d_in[5];
    const float* aU_b   = (const float*)d_in[6];
    const float* gate_w = (const float*)d_in[7];
    const float* gate_b = (const float*)d_in[8];
    const float* cb_w0 = (const float*)d_in[9],  *cb_b0 = (const float*)d_in[10];
    const float* cb_w1 = (const float*)d_in[11], *cb_b1 = (const float*)d_in[12];
    const float* cb_w2 = (const float*)d_in[13], *cb_b2 = (const float*)d_in[14];
    const float* cb_w3 = (const float*)d_in[15], *cb_b3 = (const float*)d_in[16];
    const float* cs_w0 = (const float*)d_in[17], *cs_b0 = (const float*)d_in[18];
    const float* cs_w1 = (const float*)d_in[19], *cs_b1 = (const float*)d_in[20];
    const float* cs_w2 = (const float*)d_in[21], *cs_b2 = (const float*)d_in[22];
    const float* cs_w3 = (const float*)d_in[23], *cs_b3 = (const float*)d_in[24];

    float* out = (float*)d_out;
    float* feat    = out + OFF_FEAT;
    float* oAssign = out + OFF_ASSIGN;
    float* oSeg    = out + OFF_SEG;
    float* oOut    = out + OFF_OUT;
    float* oAt     = out + OFF_AT;

    __half *xh, *wt, *bw, *fhi, *flo, *h0hi, *h0lo;
    float *preVU, *Amat, *bag, *h1;
    int* kmask;
    cudaGetSymbolAddress((void**)&xh, g_xh);
    cudaGetSymbolAddress((void**)&wt, g_wt);     cudaGetSymbolAddress((void**)&bw, g_bw);
    cudaGetSymbolAddress((void**)&fhi, g_fhi);   cudaGetSymbolAddress((void**)&flo, g_flo);
    cudaGetSymbolAddress((void**)&h0hi, g_h0hi); cudaGetSymbolAddress((void**)&h0lo, g_h0lo);
    cudaGetSymbolAddress((void**)&preVU, g_preVU);
    cudaGetSymbolAddress((void**)&Amat, g_Amat); cudaGetSymbolAddress((void**)&bag, g_bag);
    cudaGetSymbolAddress((void**)&h1, g_h1);
    cudaGetSymbolAddress((void**)&kmask, g_kmask);

    static cudaStream_t s1 = nullptr, s2 = nullptr;
    static cudaEvent_t evRoot, evWt, evW, evF0, evF1, evKm, evA, evSeg;
    if (s1 == nullptr) {
        cudaStreamCreateWithFlags(&s1, cudaStreamNonBlocking);
        cudaStreamCreateWithFlags(&s2, cudaStreamNonBlocking);
        cudaEventCreateWithFlags(&evRoot, cudaEventDisableTiming);
        cudaEventCreateWithFlags(&evWt,   cudaEventDisableTiming);
        cudaEventCreateWithFlags(&evW,    cudaEventDisableTiming);
        cudaEventCreateWithFlags(&evF0,   cudaEventDisableTiming);
        cudaEventCreateWithFlags(&evF1,   cudaEventDisableTiming);
        cudaEventCreateWithFlags(&evKm,   cudaEventDisableTiming);
        cudaEventCreateWithFlags(&evA,    cudaEventDisableTiming);
        cudaEventCreateWithFlags(&evSeg,  cudaEventDisableTiming);
    }

    const int SMB1 = 3 * 32768;   // conv: TP=0, S=3
    const int SMB2 = 2 * 49152;   // TP=1, S=2
    cudaFuncSetAttribute(mm_gemm<1, 0, 0, 3>, cudaFuncAttributeMaxDynamicSharedMemorySize, SMB1);
    cudaFuncSetAttribute(mm_gemm<0, 4, 1, 2>, cudaFuncAttributeMaxDynamicSharedMemorySize, SMB2);
    cudaFuncSetAttribute(mm_gemm<0, 2, 1, 2>, cudaFuncAttributeMaxDynamicSharedMemorySize, SMB2);
    cudaFuncSetAttribute(mm_gemm<0, 3, 1, 2>, cudaFuncAttributeMaxDynamicSharedMemorySize, SMB2);

    // fork points
    cudaEventRecord(evRoot, 0);
    cudaStreamWaitEvent(s1, evRoot, 0);
    cudaStreamWaitEvent(s2, evRoot, 0);

    // #1: convert x half0 (main); #2: convert x half1 (s2); #3: conv weights (s1)
    conv_x_k<<<32768, 256>>>((const float4*)x, (__half2*)xh);
    conv_x_k<<<32768, 256, 0, s2>>>((const float4*)x + 8388608, (__half2*)(xh + 33554432));
    splitw_conv_k<<<(L_ * KCONV) / 256, 256, 0, s1>>>(tsn_w, wt);
    cudaEventRecord(evWt, s1);

    // #4: conv half0 (main, waits weights)  [PROFILED: overall #6]
    cudaStreamWaitEvent(0, evWt, 0);
    mm_gemm<1, 0, 0, 3><<<dim3(2, 64), 256, SMB1>>>(xh, nullptr, FIN, wt, KCONV,
                                                    tsn_b, nullptr, nullptr,
                                                    feat, fhi, flo, 256, KCONV, 0);
    cudaEventRecord(evF0, 0);

    // conv half1 (s2, waits weights; co-schedules with half0)
    cudaStreamWaitEvent(s2, evWt, 0);
    mm_gemm<1, 0, 0, 3><<<dim3(2, 64), 256, SMB1, s2>>>(xh, nullptr, FIN, wt, KCONV,
                                                        tsn_b, nullptr, nullptr,
                                                        feat, fhi, flo, 256, KCONV, 8192);
    cudaEventRecord(evF1, s2);

    // remaining weight splits on s1 (overlap conv)
    splitw_pair_k<<<512, 256, 0, s1>>>(aV_w, aU_w, bw);
    splitw_gen_k<<<256, 256, 0, s1>>>(cs_w0, 257, 65536, bw + 131072);
    splitw_gen_k<<<128, 256, 0, s1>>>(cs_w1, 256, 32768, bw + 196608);
    cudaEventRecord(evW, s1);

    // kmeans on s2 after full feat (half1 on s2; wait half0)
    cudaStreamWaitEvent(s2, evF0, 0);
    kmeans_assign_k<<<B_, 1024, 0, s2>>>(feat, oAssign, kmask);
    cudaEventRecord(evKm, s2);

    // main chain: fused aV|aU -> gated (needs full feat + weights)
    cudaStreamWaitEvent(0, evF1, 0);
    cudaStreamWaitEvent(0, evW, 0);
    mm_gemm<0, 4, 1, 2><<<dim3(4, 128), 256, SMB2>>>(fhi, flo, 256, bw, 256,
                                                     aV_b, aU_b, nullptr,
                                                     preVU, nullptr, nullptr, 512, 256, 0);
    gated_kernel<<<M_ / 8, 256>>>(preVU, gate_w, gate_b, Amat);
    cudaEventRecord(evA, 0);

    // seg chain forked to s1 (parallel with softbag/bagclf)
    cudaStreamWaitEvent(s1, evA, 0);
    mm_gemm<0, 2, 1, 2><<<dim3(2, 128), 256, SMB2, s1>>>(fhi, flo, 256, bw + 131072, 256,
                                                         cs_b0, Amat, cs_w0 + 256,
                                                         nullptr, h0hi, h0lo, 256, 256, 0);
    mm_gemm<0, 3, 1, 2><<<dim3(1, 128), 256, SMB2, s1>>>(h0hi, h0lo, 256, bw + 196608, 256,
                                                         cs_b1, nullptr, nullptr,
                                                         h1, nullptr, nullptr, 128, 256, 0);
    segtail_kernel<<<M_ / 8, 256, 0, s1>>>(h1, cs_w2, cs_b2, cs_w3, cs_b3, oSeg);
    cudaEventRecord(evSeg, s1);

    // bag chain on main stream
    softbag_kernel<<<B_, 256>>>(Amat, feat, bag, oAt);
    bagclf_kernel<<<B_ / 8, 256>>>(bag, cb_w0, cb_b0, cb_w1, cb_b1,
                                   cb_w2, cb_b2, cb_w3, cb_b3, oOut);

    // join: output2 needs seg + kmeans masks
    cudaStreamWaitEvent(0, evSeg, 0);
    cudaStreamWaitEvent(0, evKm, 0);
    out2_k<<<B_ / 8, 256>>>(kmask, oSeg, oOut);
}

// round 11
// speedup vs baseline: 1.0989x; 1.0431x over previous
#include <cuda_runtime.h>
#include <cuda_fp16.h>
#include <math.h>
#include <stdint.h>

#define B_   512
#define T_   32
#define FIN  4096
#define L_   256
#define M_   (B_*T_)
#define KCONV (3*FIN)

#define OFF_FEAT   0
#define OFF_ASSIGN 4194304
#define OFF_SEG    4210688
#define OFF_OUT    4227072
#define OFF_AT     4228096

// -------- scratch (device globals) --------
__device__ __align__(16) __half g_xh[(size_t)M_ * FIN];      // x fp16
__device__ __align__(16) __half g_wt[(size_t)L_ * KCONV];    // conv weight fp16 [n][k]
__device__ __align__(16) __half g_bw[229376];                // aVU(paired)|cs0|cs1 fp16
__device__ __align__(16) __half g_fhi[(size_t)M_ * L_];      // feature fp16
__device__ __align__(16) __half g_h0hi[(size_t)M_ * 256];    // seg hidden fp16
__device__ float g_part[4 * M_];                             // gated partials [bx][m]
__device__ float g_Amat[M_];
__device__ float g_bag[B_ * L_];
__device__ float g_h1[(size_t)M_ * 128];
__device__ int   g_kmask[B_];

// ======================= helpers =======================
__device__ __forceinline__ uint32_t smem_u32(const void* p) {
    uint32_t a;
    asm("{ .reg .u64 t; cvta.to.shared.u64 t, %1; cvt.u32.u64 %0, t; }" : "=r"(a) : "l"(p));
    return a;
}
__device__ __forceinline__ void cp16(uint32_t dst, const void* src, uint32_t sz) {
    asm volatile("cp.async.cg.shared.global [%0], [%1], 16, %2;"
                 :: "r"(dst), "l"(src), "r"(sz) : "memory");
}
__device__ __forceinline__ void ldm4(uint32_t* r, uint32_t addr) {
    asm volatile("ldmatrix.sync.aligned.m8n8.x4.shared.b16 {%0,%1,%2,%3}, [%4];"
                 : "=r"(r[0]), "=r"(r[1]), "=r"(r[2]), "=r"(r[3]) : "r"(addr));
}
__device__ __forceinline__ void mma16816(float* c, const uint32_t* a, const uint32_t* b) {
    asm volatile("mma.sync.aligned.m16n8k16.row.col.f32.f16.f16.f32 "
                 "{%0,%1,%2,%3}, {%4,%5,%6,%7}, {%8,%9}, {%0,%1,%2,%3};"
                 : "+f"(c[0]), "+f"(c[1]), "+f"(c[2]), "+f"(c[3])
                 : "r"(a[0]), "r"(a[1]), "r"(a[2]), "r"(a[3]), "r"(b[0]), "r"(b[1]));
}
__device__ __forceinline__ float tanh_fast(float x) {
    float r;
    asm("tanh.approx.f32 %0, %1;" : "=f"(r) : "f"(x));
    return r;
}
__device__ __forceinline__ float sigmoid_fast(float x) {
    return __fdividef(1.f, 1.f + __expf(-x));
}

// ======================= convert / repack kernels =======================
__global__ void conv_x_k(const float4* __restrict__ x, __half2* __restrict__ o) {
    size_t i = (size_t)blockIdx.x * 256 + threadIdx.x;
    float4 v = x[i];
    __half2 a, b;
    a.x = __float2half(v.x); a.y = __float2half(v.y);
    b.x = __float2half(v.z); b.y = __float2half(v.w);
    o[2 * i] = a; o[2 * i + 1] = b;
}

__global__ void splitw_conv_k(const float* __restrict__ w, __half* __restrict__ o) {
    int idx = blockIdx.x * 256 + threadIdx.x;          // [n][k], k = tap*4096 + c
    int n = idx / KCONV;
    int k = idx - n * KCONV;
    int tap = k >> 12, c = k & 4095;
    o[idx] = __float2half(w[(size_t)n * KCONV + c * 3 + tap]);
}

// pair-interleaved: row n even -> aV_w[n/2], odd -> aU_w[n/2]
__global__ void splitw_pair_k(const float* __restrict__ wa, const float* __restrict__ wb,
                              __half* __restrict__ o) {
    int idx = blockIdx.x * 256 + threadIdx.x;          // 131072 total (512 rows x 256)
    int n = idx >> 8, k = idx & 255;
    const float* w = (n & 1) ? wb : wa;
    o[idx] = __float2half(w[(size_t)(n >> 1) * 256 + k]);
}

__global__ void splitw_gen_k(const float* __restrict__ w, int srcStride, int total,
                             __half* __restrict__ o) {
    int idx = blockIdx.x * 256 + threadIdx.x;
    if (idx >= total) return;
    int n = idx >> 8, k = idx & 255;
    o[idx] = __float2half(w[(size_t)n * srcStride + k]);
}

// ======================= HMMA GEMM (mma.sync fp16) =======================
// D[m][n] = epi( sum_k A[m][k]*B[n][k] + ... ), m = m_base + blockIdx.y*128 + ...
// TP=1: A hi/lo pair (2 passes). TP=0: single fp16 (1 pass).
// S-stage cp.async ring, one __syncthreads per chunk.
// EPI: 0 = bias, write fp32 + fp16        (conv -> feature)
//      2 = relu(bias + exCol[m]*exW[n*257]), write fp16      (seg layer0)
//      3 = relu(bias), write fp32          (seg layer1)
//      5 = fused gated: B rows pair-interleaved (even=V_d, odd=U_d), d=n>>1.
//          partial[m] += tanh(v + bias[d]) * sigmoid(u + exCol[d]) * exW[d];
//          writes Cf[blockIdx.x*M_ + m] (per-CTA partial over its 64 d's)
template<int CONV, int EPI, int TP, int S>
__global__ void __launch_bounds__(256, 2) mm_gemm(
    const __half* __restrict__ Ahi, const __half* __restrict__ Alo, int ldA,
    const __half* __restrict__ Bw, int ldB,
    const float* __restrict__ bias, const float* __restrict__ exCol,
    const float* __restrict__ exW,
    float* __restrict__ Cf, __half* __restrict__ Chi,
    int N, int K, int m_base)
{
    constexpr uint32_t STG  = TP ? 49152u : 32768u;
    constexpr uint32_t BOFF = TP ? 32768u : 16384u;
    extern __shared__ __align__(128) char smem[];
    const int tid = threadIdx.x;
    const int m0 = m_base + blockIdx.y * 128;
    const int n0 = blockIdx.x * 128;
    const uint32_t sb = smem_u32(smem);
    const int NCH = K >> 6;

    const int lane = tid & 31, warp = tid >> 5;
    const int wm = (warp >> 2) * 64, wn = (warp & 3) * 32;
    const int rsel = lane & 15, ksel = lane >> 4;

    float acc[4][4][4];
#pragma unroll
    for (int i = 0; i < 4; i++)
#pragma unroll
        for (int j = 0; j < 4; j++)
#pragma unroll
            for (int u = 0; u < 4; u++) acc[i][j][u] = 0.f;

    auto issue_load = [&](int ch) {
        const uint32_t slot = (uint32_t)(ch % S);
        const int k0 = ch << 6;
        if (tid < 128) {
            const int row = tid;
            const __half *srcH, *srcL = nullptr;
            uint32_t sz = 16;
            if (CONV) {
                const int tap = k0 >> 12;
                const int coff = k0 & 4095;
                long sr = (long)m0 + row + tap - 1;
                const int tt = (row & 31) + tap - 1;
                if (tt < 0 || tt > 31) { sz = 0; sr = m0 + row; }
                srcH = Ahi + sr * ldA + coff;
                if (TP) srcL = Alo + sr * ldA + coff;
            } else {
                srcH = Ahi + (size_t)(m0 + row) * ldA + k0;
                if (TP) srcL = Alo + (size_t)(m0 + row) * ldA + k0;
            }
            const uint32_t d = sb + slot * STG + row * 128;
            const int xm = row & 7;
#pragma unroll
            for (int c = 0; c < 8; c++) {
                const uint32_t cc = (uint32_t)((c ^ xm) << 4);
                cp16(d + cc, srcH + c * 8, sz);
                if (TP) cp16(d + 16384 + cc, srcL + c * 8, sz);
            }
        } else {
            const int row = tid - 128;
            const __half* srcB = Bw + (size_t)(n0 + row) * ldB + k0;
            const uint32_t d = sb + slot * STG + BOFF + row * 128;
            const int xm = row & 7;
#pragma unroll
            for (int c = 0; c < 8; c++) {
                const uint32_t cc = (uint32_t)((c ^ xm) << 4);
                cp16(d + cc, srcB + c * 8, 16);
            }
        }
        asm volatile("cp.async.commit_group;" ::: "memory");
    };

#pragma unroll
    for (int i = 0; i < S - 1; i++) issue_load(i);

    for (int ch = 0; ch < NCH; ch++) {
        if (ch + S - 2 < NCH - 1)
            asm volatile("cp.async.wait_group %0;" :: "n"(S - 2) : "memory");
        else
            asm volatile("cp.async.wait_group 0;" ::: "memory");
        __syncthreads();
        if (ch + S - 1 < NCH) issue_load(ch + S - 1);

        const uint32_t base = sb + (uint32_t)(ch % S) * STG;
#pragma unroll
        for (int ks = 0; ks < 4; ks++) {
            const int kc = ks * 2 + ksel;
            uint32_t ah[4][4], al[4][4];
#pragma unroll
            for (int im = 0; im < 4; im++) {
                const int row = wm + im * 16 + rsel;
                const uint32_t a = base + row * 128 + (uint32_t)(((kc ^ (row & 7))) << 4);
                ldm4(ah[im], a);
                if (TP) ldm4(al[im], a + 16384);
            }
            uint32_t bh[4][2];
#pragma unroll
            for (int j2 = 0; j2 < 2; j2++) {
                const int row = wn + j2 * 16 + rsel;
                const uint32_t a = base + BOFF + row * 128 + (uint32_t)(((kc ^ (row & 7))) << 4);
                uint32_t t[4];
                ldm4(t, a);
                bh[j2 * 2][0] = t[0]; bh[j2 * 2][1] = t[2];
                bh[j2 * 2 + 1][0] = t[1]; bh[j2 * 2 + 1][1] = t[3];
            }
#pragma unroll
            for (int im = 0; im < 4; im++)
#pragma unroll
                for (int jn = 0; jn < 4; jn++) {
                    mma16816(acc[im][jn], ah[im], bh[jn]);
                    if (TP) mma16816(acc[im][jn], al[im], bh[jn]);
                }
        }
    }

    const int g = lane >> 2, t4 = lane & 3;

    if (EPI == 5) {
        // fused gated epilogue: per-thread partials over its 4 d's per (im,h) row
        float part[4][2];
#pragma unroll
        for (int im = 0; im < 4; im++)
#pragma unroll
            for (int h = 0; h < 2; h++) {
                float p = 0.f;
#pragma unroll
                for (int jn = 0; jn < 4; jn++) {
                    const int n = n0 + wn + jn * 8 + t4 * 2;
                    const int d = n >> 1;
                    float v = acc[im][jn][h * 2 + 0] + bias[d];
                    float u = acc[im][jn][h * 2 + 1] + exCol[d];
                    p += tanh_fast(v) * sigmoid_fast(u) * exW[d];
                }
                // reduce over the 4 t4-lanes sharing this row
                p += __shfl_xor_sync(0xffffffffu, p, 1);
                p += __shfl_xor_sync(0xffffffffu, p, 2);
                part[im][h] = p;
            }
        __syncthreads();   // pipeline smem now reusable
        float* sred = reinterpret_cast<float*>(smem);
        if (t4 == 0) {
#pragma unroll
            for (int im = 0; im < 4; im++)
#pragma unroll
                for (int h = 0; h < 2; h++) {
                    const int lm = wm + im * 16 + g + h * 8;   // 0..127
                    sred[(warp & 3) * 128 + lm] = part[im][h];
                }
        }
        __syncthreads();
        if (tid < 128) {
            float s = sred[tid] + sred[128 + tid] + sred[256 + tid] + sred[384 + tid];
            Cf[(size_t)blockIdx.x * M_ + m0 + tid] = s;
        }
        return;
    }

    // ---- standard epilogue ----
#pragma unroll
    for (int im = 0; im < 4; im++) {
#pragma unroll
        for (int jn = 0; jn < 4; jn++) {
            const int n = n0 + wn + jn * 8 + t4 * 2;
            const float bv0 = bias[n], bv1 = bias[n + 1];
            float ew0 = 0.f, ew1 = 0.f;
            if (EPI == 2) { ew0 = exW[(size_t)n * 257]; ew1 = exW[(size_t)(n + 1) * 257]; }
#pragma unroll
            for (int h = 0; h < 2; h++) {
                const int m = m0 + wm + im * 16 + g + h * 8;
                float v0 = acc[im][jn][h * 2 + 0] + bv0;
                float v1 = acc[im][jn][h * 2 + 1] + bv1;
                if (EPI == 2) {
                    const float ec = exCol[m];
                    v0 += ec * ew0; v1 += ec * ew1;
                }
                if (EPI == 2 || EPI == 3) { v0 = fmaxf(v0, 0.f); v1 = fmaxf(v1, 0.f); }
                const size_t off = (size_t)m * N + n;
                if (EPI != 2)
                    *reinterpret_cast<float2*>(Cf + off) = make_float2(v0, v1);
                if (EPI == 0 || EPI == 2) {
                    __half2 ph;
                    ph.x = __float2half(v0); ph.y = __float2half(v1);
                    *reinterpret_cast<__half2*>(Chi + off) = ph;
                }
            }
        }
    }
}

// ======================= gated final combine =======================
__global__ void __launch_bounds__(256) gatedfin_k(
    const float* __restrict__ part, const float* __restrict__ gb,
    float* __restrict__ Amat)
{
    int m = blockIdx.x * 256 + threadIdx.x;
    Amat[m] = part[m] + part[M_ + m] + part[2 * M_ + m] + part[3 * M_ + m] + gb[0];
}

// ======================= softmax over T + bag + At =======================
__global__ void __launch_bounds__(256) softbag_kernel(
    const float* __restrict__ Amat, const float* __restrict__ feat,
    float* __restrict__ bag, float* __restrict__ outAt)
{
    __shared__ float p[32];
    int b = blockIdx.x;
    int tid = threadIdx.x;
    if (tid < 32) {
        float v = Amat[b * 32 + tid];
        outAt[b * 32 + tid] = v;
        float mx = v;
#pragma unroll
        for (int o = 16; o; o >>= 1) mx = fmaxf(mx, __shfl_xor_sync(0xffffffffu, mx, o));
        float e = expf(v - mx);
        float s = e;
#pragma unroll
        for (int o = 16; o; o >>= 1) s += __shfl_xor_sync(0xffffffffu, s, o);
        p[tid] = e / s;
    }
    __syncthreads();
    float acc = 0.f;
#pragma unroll 8
    for (int t = 0; t < 32; t++) acc += p[t] * feat[(size_t)(b * 32 + t) * 256 + tid];
    bag[b * 256 + tid] = acc;
}

// ======================= bag classifier =======================
__global__ void __launch_bounds__(256) bagclf_kernel(
    const float* __restrict__ bag,
    const float* __restrict__ w0, const float* __restrict__ b0,
    const float* __restrict__ w1, const float* __restrict__ b1,
    const float* __restrict__ w2, const float* __restrict__ b2,
    const float* __restrict__ w3, const float* __restrict__ b3,
    float* __restrict__ outp)
{
    __shared__ float sb[8 * 256];
    __shared__ float sh[8 * 256];
    int base = blockIdx.x * 8;
    int tid = threadIdx.x;
#pragma unroll
    for (int i = 0; i < 8; i++) sb[tid + i * 256] = bag[(size_t)base * 256 + tid + i * 256];
    __syncthreads();
    {
        float acc[8] = {0, 0, 0, 0, 0, 0, 0, 0};
        const float* w = w0 + (size_t)tid * 256;
        for (int l = 0; l < 256; l++) {
            float wv = w[l];
#pragma unroll
            for (int r = 0; r < 8; r++) acc[r] += wv * sb[r * 256 + l];
        }
        float bb = b0[tid];
#pragma unroll
        for (int r = 0; r < 8; r++) sh[r * 256 + tid] = fmaxf(acc[r] + bb, 0.f);
    }
    __syncthreads();
    if (tid < 128) {
        float acc[8] = {0, 0, 0, 0, 0, 0, 0, 0};
        const float* w = w1 + (size_t)tid * 256;
        for (int l = 0; l < 256; l++) {
            float wv = w[l];
#pragma unroll
            for (int r = 0; r < 8; r++) acc[r] += wv * sh[r * 256 + l];
        }
        float bb = b1[tid];
#pragma unroll
        for (int r = 0; r < 8; r++) sb[r * 128 + tid] = fmaxf(acc[r] + bb, 0.f);
    }
    __syncthreads();
    if (tid < 32) {
        float acc[8] = {0, 0, 0, 0, 0, 0, 0, 0};
        const float* w = w2 + (size_t)tid * 128;
        for (int l = 0; l < 128; l++) {
            float wv = w[l];
#pragma unroll
            for (int r = 0; r < 8; r++) acc[r] += wv * sb[r * 128 + l];
        }
        float bb = b2[tid];
#pragma unroll
        for (int r = 0; r < 8; r++) sh[r * 32 + tid] = fmaxf(acc[r] + bb, 0.f);
    }
    __syncthreads();
    if (tid < 8) {
        float a = 0.f;
        for (int j = 0; j < 32; j++) a += w3[j] * sh[tid * 32 + j];
        float o1 = 1.f / (1.f + expf(-(a + b3[0])));
        outp[(size_t)(base + tid) * 2 + 0] = 0.5f * o1;
    }
}

// ======================= seg tail =======================
__global__ void __launch_bounds__(256) segtail_kernel(
    const float* __restrict__ h1,
    const float* __restrict__ w2, const float* __restrict__ b2,
    const float* __restrict__ w3, const float* __restrict__ b3,
    float* __restrict__ out_seg)
{
    __shared__ float sw2[128 * 32];
    __shared__ float sh1[8 * 128];
    int m0 = blockIdx.x * 8;
    int tid = threadIdx.x;
#pragma unroll
    for (int i = 0; i < 16; i++) {
        int idx = tid + i * 256;
        sw2[(idx & 127) * 32 + (idx >> 7)] = w2[idx];
    }
#pragma unroll
    for (int i = 0; i < 4; i++) {
        int idx = tid + i * 256;
        sh1[idx] = h1[(size_t)m0 * 128 + idx];
    }
    __syncthreads();
    int r = tid >> 5, j = tid & 31;
    float acc = b2[j];
#pragma unroll 8
    for (int l = 0; l < 128; l++) acc += sw2[l * 32 + j] * sh1[r * 128 + l];
    float h2 = fmaxf(acc, 0.f);
    float v = h2 * w3[j];
#pragma unroll
    for (int o = 16; o; o >>= 1) v += __shfl_xor_sync(0xffffffffu, v, o);
    if (j == 0) out_seg[m0 + r] = 1.f / (1.f + expf(-(v + b3[0])));
}

// ======================= per-sample 2-means (assign only; overlappable) ============
__global__ void __launch_bounds__(1024) kmeans_assign_k(
    const float* __restrict__ feat,
    float* __restrict__ out_assign, int* __restrict__ out_mask)
{
    __shared__ float sf[32 * 256];
    __shared__ float sc[2 * 256];
    __shared__ float sdiff[256];
    __shared__ float sinv[2];
    __shared__ int sassign[32];
    __shared__ unsigned smask;
    int b = blockIdx.x;
    int tid = threadIdx.x;
    int lane = tid & 31, w = tid >> 5;

    {
        const float4* src = reinterpret_cast<const float4*>(feat + (size_t)b * 8192);
        float4* dst = reinterpret_cast<float4*>(sf);
        dst[tid] = src[tid];
        dst[tid + 1024] = src[tid + 1024];
    }
    __syncthreads();
    if (tid < 256) {
        sc[tid] = sf[tid];
        sc[256 + tid] = sf[4096 + tid];
    }
    __syncthreads();

    unsigned prev1 = 0, prev2 = 0;
    unsigned final_mask = 0;
    for (int it = 0; it < 100; it++) {
        if (w < 2) {
            float s = 0.f;
#pragma unroll
            for (int i = 0; i < 8; i++) {
                float v = sc[w * 256 + lane + i * 32];
                s += v * v;
            }
#pragma unroll
            for (int o = 16; o; o >>= 1) s += __shfl_xor_sync(0xffffffffu, s, o);
            if (lane == 0) sinv[w] = 1.f / (sqrtf(s) + 1e-8f);
        }
        __syncthreads();
        if (tid < 256) sdiff[tid] = sc[256 + tid] * sinv[1] - sc[tid] * sinv[0];
        __syncthreads();
        {
            float s = 0.f;
#pragma unroll
            for (int i = 0; i < 8; i++)
                s += sf[w * 256 + lane + i * 32] * sdiff[lane + i * 32];
#pragma unroll
            for (int o = 16; o; o >>= 1) s += __shfl_xor_sync(0xffffffffu, s, o);
            if (lane == 0) sassign[w] = (s > 0.f) ? 1 : 0;
        }
        __syncthreads();
        if (w == 0) {
            unsigned mk = __ballot_sync(0xffffffffu, sassign[lane] != 0);
            if (lane == 0) smask = mk;
        }
        __syncthreads();
        unsigned mask = smask;
        if (it >= 1 && mask == prev1) { final_mask = mask; break; }
        if (it >= 2 && mask == prev2) {
            final_mask = (((99 - it) & 1) == 0) ? mask : prev1;
            break;
        }
        prev2 = prev1; prev1 = mask; final_mask = mask;
        if (it == 99) break;
        if (tid < 256) {
            int cnt1 = __popc(mask);
            int cnt0 = 32 - cnt1;
            float a0 = 0.f, a1 = 0.f;
#pragma unroll
            for (int t = 0; t < 32; t++) {
                float fv = sf[t * 256 + tid];
                if ((mask >> t) & 1) a1 += fv; else a0 += fv;
            }
            if (cnt0 > 0) sc[tid] = a0 / (float)cnt0;
            if (cnt1 > 0) sc[256 + tid] = a1 / (float)cnt1;
        }
        __syncthreads();
    }

    if (tid < 32) {
        out_assign[b * 32 + tid] = (float)((final_mask >> tid) & 1);
        if (tid == 0) out_mask[b] = (int)final_mask;
    }
}

// ======================= output2 join =======================
__global__ void __launch_bounds__(256) out2_k(
    const int* __restrict__ mask_arr, const float* __restrict__ seg,
    float* __restrict__ outp)
{
    int b = blockIdx.x * 8 + (threadIdx.x >> 5);
    int lane = threadIdx.x & 31;
    unsigned mask = (unsigned)mask_arr[b];
    float s = seg[b * 32 + lane];
    int bit = (mask >> lane) & 1;
    float v0 = bit ? 0.f : s;
    float v1 = bit ? s : 0.f;
#pragma unroll
    for (int o = 16; o; o >>= 1) {
        v0 += __shfl_xor_sync(0xffffffffu, v0, o);
        v1 += __shfl_xor_sync(0xffffffffu, v1, o);
    }
    if (lane == 0) {
        int cnt1 = __popc(mask);
        int cnt0 = 32 - cnt1;
        float m0 = (cnt0 > 0) ? v0 / (float)cnt0 : -INFINITY;
        float m1 = (cnt1 > 0) ? v1 / (float)cnt1 : -INFINITY;
        outp[(size_t)b * 2 + 1] = 0.5f * fmaxf(m0, m1);
    }
}

// ======================= launch =======================
extern "C" void kernel_launch(void* const* d_in, const int* in_sizes, int n_in,
                              void* d_out, int out_size)
{
    const float* x      = (const float*)d_in[0];
    const float* tsn_w  = (const float*)d_in[1];
    const float* tsn_b  = (const float*)d_in[2];
    const float* aV_w   = (const float*)d_in[3];
    const float* aV_b   = (const float*)d_in[4];
    const float* aU_w   = (const float*)d_in[5];
    const float* aU_b   = (const float*)d_in[6];
    const float* gate_w = (const float*)d_in[7];
    const float* gate_b = (const float*)d_in[8];
    const float* cb_w0 = (const float*)d_in[9],  *cb_b0 = (const float*)d_in[10];
    const float* cb_w1 = (const float*)d_in[11], *cb_b1 = (const float*)d_in[12];
    const float* cb_w2 = (const float*)d_in[13], *cb_b2 = (const float*)d_in[14];
    const float* cb_w3 = (const float*)d_in[15], *cb_b3 = (const float*)d_in[16];
    const float* cs_w0 = (const float*)d_in[17], *cs_b0 = (const float*)d_in[18];
    const float* cs_w1 = (const float*)d_in[19], *cs_b1 = (const float*)d_in[20];
    const float* cs_w2 = (const float*)d_in[21], *cs_b2 = (const float*)d_in[22];
    const float* cs_w3 = (const float*)d_in[23], *cs_b3 = (const float*)d_in[24];

    float* out = (float*)d_out;
    float* feat    = out + OFF_FEAT;
    float* oAssign = out + OFF_ASSIGN;
    float* oSeg    = out + OFF_SEG;
    float* oOut    = out + OFF_OUT;
    float* oAt     = out + OFF_AT;

    __half *xh, *wt, *bw, *fhi, *h0hi;
    float *part, *Amat, *bag, *h1;
    int* kmask;
    cudaGetSymbolAddress((void**)&xh, g_xh);
    cudaGetSymbolAddress((void**)&wt, g_wt);     cudaGetSymbolAddress((void**)&bw, g_bw);
    cudaGetSymbolAddress((void**)&fhi, g_fhi);   cudaGetSymbolAddress((void**)&h0hi, g_h0hi);
    cudaGetSymbolAddress((void**)&part, g_part);
    cudaGetSymbolAddress((void**)&Amat, g_Amat); cudaGetSymbolAddress((void**)&bag, g_bag);
    cudaGetSymbolAddress((void**)&h1, g_h1);
    cudaGetSymbolAddress((void**)&kmask, g_kmask);

    static cudaStream_t s1 = nullptr, s2 = nullptr;
    static cudaEvent_t evRoot, evX0, evX1, evWt, evW, evF0, evF1, evKm, evA, evSeg;
    if (s1 == nullptr) {
        cudaStreamCreateWithFlags(&s1, cudaStreamNonBlocking);
        cudaStreamCreateWithFlags(&s2, cudaStreamNonBlocking);
        cudaEventCreateWithFlags(&evRoot, cudaEventDisableTiming);
        cudaEventCreateWithFlags(&evX0,   cudaEventDisableTiming);
        cudaEventCreateWithFlags(&evX1,   cudaEventDisableTiming);
        cudaEventCreateWithFlags(&evWt,   cudaEventDisableTiming);
        cudaEventCreateWithFlags(&evW,    cudaEventDisableTiming);
        cudaEventCreateWithFlags(&evF0,   cudaEventDisableTiming);
        cudaEventCreateWithFlags(&evF1,   cudaEventDisableTiming);
        cudaEventCreateWithFlags(&evKm,   cudaEventDisableTiming);
        cudaEventCreateWithFlags(&evA,    cudaEventDisableTiming);
        cudaEventCreateWithFlags(&evSeg,  cudaEventDisableTiming);
    }

    const int SMB1 = 3 * 32768;   // conv: TP=0, S=3
    const int SMB0 = 2 * 32768;   // small GEMMs: TP=0, S=2
    cudaFuncSetAttribute(mm_gemm<1, 0, 0, 3>, cudaFuncAttributeMaxDynamicSharedMemorySize, SMB1);
    cudaFuncSetAttribute(mm_gemm<0, 5, 0, 2>, cudaFuncAttributeMaxDynamicSharedMemorySize, SMB0);
    cudaFuncSetAttribute(mm_gemm<0, 2, 0, 2>, cudaFuncAttributeMaxDynamicSharedMemorySize, SMB0);
    cudaFuncSetAttribute(mm_gemm<0, 3, 0, 2>, cudaFuncAttributeMaxDynamicSharedMemorySize, SMB0);

    // fork points
    cudaEventRecord(evRoot, 0);
    cudaStreamWaitEvent(s1, evRoot, 0);
    cudaStreamWaitEvent(s2, evRoot, 0);

    // #1: x half0 (main); #2: x half1 (s2); #3: conv weights (s1)
    conv_x_k<<<32768, 256>>>((const float4*)x, (__half2*)xh);
    cudaEventRecord(evX0, 0);
    conv_x_k<<<32768, 256, 0, s2>>>((const float4*)x + 8388608, (__half2*)(xh + 33554432));
    cudaEventRecord(evX1, s2);
    splitw_conv_k<<<(L_ * KCONV) / 256, 256, 0, s1>>>(tsn_w, wt);
    cudaEventRecord(evWt, s1);

    // #4: conv half0 (main; waits weights + other half's x)  [PROFILED: overall #6]
    cudaStreamWaitEvent(0, evWt, 0);
    cudaStreamWaitEvent(0, evX1, 0);
    mm_gemm<1, 0, 0, 3><<<dim3(2, 64), 256, SMB1>>>(xh, nullptr, FIN, wt, KCONV,
                                                    tsn_b, nullptr, nullptr,
                                                    feat, fhi, 256, KCONV, 0);
    cudaEventRecord(evF0, 0);

    // conv half1 (s2; waits weights + half0's x)
    cudaStreamWaitEvent(s2, evWt, 0);
    cudaStreamWaitEvent(s2, evX0, 0);
    mm_gemm<1, 0, 0, 3><<<dim3(2, 64), 256, SMB1, s2>>>(xh, nullptr, FIN, wt, KCONV,
                                                        tsn_b, nullptr, nullptr,
                                                        feat, fhi, 256, KCONV, 8192);
    cudaEventRecord(evF1, s2);

    // remaining weight repacks on s1 (overlap conv)
    splitw_pair_k<<<512, 256, 0, s1>>>(aV_w, aU_w, bw);
    splitw_gen_k<<<256, 256, 0, s1>>>(cs_w0, 257, 65536, bw + 131072);
    splitw_gen_k<<<128, 256, 0, s1>>>(cs_w1, 256, 32768, bw + 196608);
    cudaEventRecord(evW, s1);

    // kmeans on s2 after full feat
    cudaStreamWaitEvent(s2, evF0, 0);
    kmeans_assign_k<<<B_, 1024, 0, s2>>>(feat, oAssign, kmask);
    cudaEventRecord(evKm, s2);

    // main chain: fused aVU+gated (EPI5, 1-pass) -> partials -> Amat
    cudaStreamWaitEvent(0, evF1, 0);
    cudaStreamWaitEvent(0, evW, 0);
    mm_gemm<0, 5, 0, 2><<<dim3(4, 128), 256, SMB0>>>(fhi, nullptr, 256, bw, 256,
                                                     aV_b, aU_b, gate_w,
                                                     part, nullptr, 512, 256, 0);
    gatedfin_k<<<M_ / 256, 256>>>(part, gate_b, Amat);
    cudaEventRecord(evA, 0);

    // seg chain on s1 (parallel with softbag/bagclf), all 1-pass
    cudaStreamWaitEvent(s1, evA, 0);
    mm_gemm<0, 2, 0, 2><<<dim3(2, 128), 256, SMB0, s1>>>(fhi, nullptr, 256, bw + 131072, 256,
                                                         cs_b0, Amat, cs_w0 + 256,
                                                         nullptr, h0hi, 256, 256, 0);
    mm_gemm<0, 3, 0, 2><<<dim3(1, 128), 256, SMB0, s1>>>(h0hi, nullptr, 256, bw + 196608, 256,
                                                         cs_b1, nullptr, nullptr,
                                                         h1, nullptr, 128, 256, 0);
    segtail_kernel<<<M_ / 8, 256, 0, s1>>>(h1, cs_w2, cs_b2, cs_w3, cs_b3, oSeg);
    cudaEventRecord(evSeg, s1);

    // bag chain on main stream
    softbag_kernel<<<B_, 256>>>(Amat, feat, bag, oAt);
    bagclf_kernel<<<B_ / 8, 256>>>(bag, cb_w0, cb_b0, cb_w1, cb_b1,
                                   cb_w2, cb_b2, cb_w3, cb_b3, oOut);

    // join: output2 needs seg + kmeans masks
    cudaStreamWaitEvent(0, evSeg, 0);
    cudaStreamWaitEvent(0, evKm, 0);
    out2_k<<<B_ / 8, 256>>>(kmask, oSeg, oOut);
}

// round 12
// speedup vs baseline: 1.1019x; 1.0028x over previous
#include <cuda_runtime.h>
#include <cuda_fp16.h>
#include <math.h>
#include <stdint.h>

#define B_   512
#define T_   32
#define FIN  4096
#define L_   256
#define M_   (B_*T_)
#define KCONV (3*FIN)

#define OFF_FEAT   0
#define OFF_ASSIGN 4194304
#define OFF_SEG    4210688
#define OFF_OUT    4227072
#define OFF_AT     4228096

// -------- scratch (device globals) --------
__device__ __align__(16) __half g_xh[(size_t)M_ * FIN];      // x fp16
__device__ __align__(16) __half g_wt[(size_t)L_ * KCONV];    // conv weight fp16 [n][k]
__device__ __align__(16) __half g_bw[229376];                // aVU(paired)|cs0|cs1 fp16
__device__ __align__(16) __half g_fhi[(size_t)M_ * L_];      // feature fp16
__device__ __align__(16) __half g_h0hi[(size_t)M_ * 256];    // seg hidden fp16
__device__ float g_part[4 * M_];                             // gated partials [bx][m]
__device__ float g_Amat[M_];
__device__ float g_bag[B_ * L_];
__device__ float g_h1[(size_t)M_ * 128];
__device__ int   g_kmask[B_];

// ======================= helpers =======================
__device__ __forceinline__ uint32_t smem_u32(const void* p) {
    uint32_t a;
    asm("{ .reg .u64 t; cvta.to.shared.u64 t, %1; cvt.u32.u64 %0, t; }" : "=r"(a) : "l"(p));
    return a;
}
__device__ __forceinline__ void cp16(uint32_t dst, const void* src, uint32_t sz) {
    asm volatile("cp.async.cg.shared.global [%0], [%1], 16, %2;"
                 :: "r"(dst), "l"(src), "r"(sz) : "memory");
}
__device__ __forceinline__ void ldm4(uint32_t* r, uint32_t addr) {
    asm volatile("ldmatrix.sync.aligned.m8n8.x4.shared.b16 {%0,%1,%2,%3}, [%4];"
                 : "=r"(r[0]), "=r"(r[1]), "=r"(r[2]), "=r"(r[3]) : "r"(addr));
}
__device__ __forceinline__ void mma16816(float* c, const uint32_t* a, const uint32_t* b) {
    asm volatile("mma.sync.aligned.m16n8k16.row.col.f32.f16.f16.f32 "
                 "{%0,%1,%2,%3}, {%4,%5,%6,%7}, {%8,%9}, {%0,%1,%2,%3};"
                 : "+f"(c[0]), "+f"(c[1]), "+f"(c[2]), "+f"(c[3])
                 : "r"(a[0]), "r"(a[1]), "r"(a[2]), "r"(a[3]), "r"(b[0]), "r"(b[1]));
}
__device__ __forceinline__ float tanh_fast(float x) {
    float r;
    asm("tanh.approx.f32 %0, %1;" : "=f"(r) : "f"(x));
    return r;
}
__device__ __forceinline__ float sigmoid_fast(float x) {
    return __fdividef(1.f, 1.f + __expf(-x));
}

// ======================= convert / repack kernels =======================
__global__ void conv_x_k(const float4* __restrict__ x, __half2* __restrict__ o) {
    size_t i = (size_t)blockIdx.x * 256 + threadIdx.x;
    float4 v = x[i];
    __half2 a, b;
    a.x = __float2half(v.x); a.y = __float2half(v.y);
    b.x = __float2half(v.z); b.y = __float2half(v.w);
    o[2 * i] = a; o[2 * i + 1] = b;
}

__global__ void splitw_conv_k(const float* __restrict__ w, __half* __restrict__ o) {
    int idx = blockIdx.x * 256 + threadIdx.x;          // [n][k], k = tap*4096 + c
    int n = idx / KCONV;
    int k = idx - n * KCONV;
    int tap = k >> 12, c = k & 4095;
    o[idx] = __float2half(w[(size_t)n * KCONV + c * 3 + tap]);
}

// pair-interleaved: row n even -> aV_w[n/2], odd -> aU_w[n/2]
__global__ void splitw_pair_k(const float* __restrict__ wa, const float* __restrict__ wb,
                              __half* __restrict__ o) {
    int idx = blockIdx.x * 256 + threadIdx.x;          // 131072 total (512 rows x 256)
    int n = idx >> 8, k = idx & 255;
    const float* w = (n & 1) ? wb : wa;
    o[idx] = __float2half(w[(size_t)(n >> 1) * 256 + k]);
}

__global__ void splitw_gen_k(const float* __restrict__ w, int srcStride, int total,
                             __half* __restrict__ o) {
    int idx = blockIdx.x * 256 + threadIdx.x;
    if (idx >= total) return;
    int n = idx >> 8, k = idx & 255;
    o[idx] = __float2half(w[(size_t)n * srcStride + k]);
}

// ======================= HMMA GEMM (mma.sync fp16) =======================
// D[m][n] = epi( sum_k A[m][k]*B[n][k] + ... ), m = m_base + blockIdx.y*128 + ...
// TP=1: A hi/lo pair (2 passes). TP=0: single fp16 (1 pass).
// S-stage cp.async ring, one __syncthreads per chunk.
// EPI: 0 = bias, write fp32 + fp16        (conv -> feature)
//      2 = relu(bias + exCol[m]*exW[n*257]), write fp16      (seg layer0)
//      3 = relu(bias), write fp32          (seg layer1)
//      5 = fused gated (pair-interleaved V/U rows)
template<int CONV, int EPI, int TP, int S>
__global__ void __launch_bounds__(256, 2) mm_gemm(
    const __half* __restrict__ Ahi, const __half* __restrict__ Alo, int ldA,
    const __half* __restrict__ Bw, int ldB,
    const float* __restrict__ bias, const float* __restrict__ exCol,
    const float* __restrict__ exW,
    float* __restrict__ Cf, __half* __restrict__ Chi,
    int N, int K, int m_base)
{
    constexpr uint32_t STG  = TP ? 49152u : 32768u;
    constexpr uint32_t BOFF = TP ? 32768u : 16384u;
    extern __shared__ __align__(128) char smem[];
    const int tid = threadIdx.x;
    const int m0 = m_base + blockIdx.y * 128;
    const int n0 = blockIdx.x * 128;
    const uint32_t sb = smem_u32(smem);
    const int NCH = K >> 6;

    const int lane = tid & 31, warp = tid >> 5;
    const int wm = (warp >> 2) * 64, wn = (warp & 3) * 32;
    const int rsel = lane & 15, ksel = lane >> 4;

    float acc[4][4][4];
#pragma unroll
    for (int i = 0; i < 4; i++)
#pragma unroll
        for (int j = 0; j < 4; j++)
#pragma unroll
            for (int u = 0; u < 4; u++) acc[i][j][u] = 0.f;

    auto issue_load = [&](int ch) {
        const uint32_t slot = (uint32_t)(ch % S);
        const int k0 = ch << 6;
        if (tid < 128) {
            const int row = tid;
            const __half *srcH, *srcL = nullptr;
            uint32_t sz = 16;
            if (CONV) {
                const int tap = k0 >> 12;
                const int coff = k0 & 4095;
                long sr = (long)m0 + row + tap - 1;
                const int tt = (row & 31) + tap - 1;
                if (tt < 0 || tt > 31) { sz = 0; sr = m0 + row; }
                srcH = Ahi + sr * ldA + coff;
                if (TP) srcL = Alo + sr * ldA + coff;
            } else {
                srcH = Ahi + (size_t)(m0 + row) * ldA + k0;
                if (TP) srcL = Alo + (size_t)(m0 + row) * ldA + k0;
            }
            const uint32_t d = sb + slot * STG + row * 128;
            const int xm = row & 7;
#pragma unroll
            for (int c = 0; c < 8; c++) {
                const uint32_t cc = (uint32_t)((c ^ xm) << 4);
                cp16(d + cc, srcH + c * 8, sz);
                if (TP) cp16(d + 16384 + cc, srcL + c * 8, sz);
            }
        } else {
            const int row = tid - 128;
            const __half* srcB = Bw + (size_t)(n0 + row) * ldB + k0;
            const uint32_t d = sb + slot * STG + BOFF + row * 128;
            const int xm = row & 7;
#pragma unroll
            for (int c = 0; c < 8; c++) {
                const uint32_t cc = (uint32_t)((c ^ xm) << 4);
                cp16(d + cc, srcB + c * 8, 16);
            }
        }
        asm volatile("cp.async.commit_group;" ::: "memory");
    };

#pragma unroll
    for (int i = 0; i < S - 1; i++) issue_load(i);

    for (int ch = 0; ch < NCH; ch++) {
        if (ch + S - 2 < NCH - 1)
            asm volatile("cp.async.wait_group %0;" :: "n"(S - 2) : "memory");
        else
            asm volatile("cp.async.wait_group 0;" ::: "memory");
        __syncthreads();
        if (ch + S - 1 < NCH) issue_load(ch + S - 1);

        const uint32_t base = sb + (uint32_t)(ch % S) * STG;
#pragma unroll
        for (int ks = 0; ks < 4; ks++) {
            const int kc = ks * 2 + ksel;
            uint32_t ah[4][4], al[4][4];
#pragma unroll
            for (int im = 0; im < 4; im++) {
                const int row = wm + im * 16 + rsel;
                const uint32_t a = base + row * 128 + (uint32_t)(((kc ^ (row & 7))) << 4);
                ldm4(ah[im], a);
                if (TP) ldm4(al[im], a + 16384);
            }
            uint32_t bh[4][2];
#pragma unroll
            for (int j2 = 0; j2 < 2; j2++) {
                const int row = wn + j2 * 16 + rsel;
                const uint32_t a = base + BOFF + row * 128 + (uint32_t)(((kc ^ (row & 7))) << 4);
                uint32_t t[4];
                ldm4(t, a);
                bh[j2 * 2][0] = t[0]; bh[j2 * 2][1] = t[2];
                bh[j2 * 2 + 1][0] = t[1]; bh[j2 * 2 + 1][1] = t[3];
            }
#pragma unroll
            for (int im = 0; im < 4; im++)
#pragma unroll
                for (int jn = 0; jn < 4; jn++) {
                    mma16816(acc[im][jn], ah[im], bh[jn]);
                    if (TP) mma16816(acc[im][jn], al[im], bh[jn]);
                }
        }
    }

    const int g = lane >> 2, t4 = lane & 3;

    if (EPI == 5) {
        float part[4][2];
#pragma unroll
        for (int im = 0; im < 4; im++)
#pragma unroll
            for (int h = 0; h < 2; h++) {
                float p = 0.f;
#pragma unroll
                for (int jn = 0; jn < 4; jn++) {
                    const int n = n0 + wn + jn * 8 + t4 * 2;
                    const int d = n >> 1;
                    float v = acc[im][jn][h * 2 + 0] + bias[d];
                    float u = acc[im][jn][h * 2 + 1] + exCol[d];
                    p += tanh_fast(v) * sigmoid_fast(u) * exW[d];
                }
                p += __shfl_xor_sync(0xffffffffu, p, 1);
                p += __shfl_xor_sync(0xffffffffu, p, 2);
                part[im][h] = p;
            }
        __syncthreads();
        float* sred = reinterpret_cast<float*>(smem);
        if (t4 == 0) {
#pragma unroll
            for (int im = 0; im < 4; im++)
#pragma unroll
                for (int h = 0; h < 2; h++) {
                    const int lm = wm + im * 16 + g + h * 8;
                    sred[(warp & 3) * 128 + lm] = part[im][h];
                }
        }
        __syncthreads();
        if (tid < 128) {
            float s = sred[tid] + sred[128 + tid] + sred[256 + tid] + sred[384 + tid];
            Cf[(size_t)blockIdx.x * M_ + m0 + tid] = s;
        }
        return;
    }

#pragma unroll
    for (int im = 0; im < 4; im++) {
#pragma unroll
        for (int jn = 0; jn < 4; jn++) {
            const int n = n0 + wn + jn * 8 + t4 * 2;
            const float bv0 = bias[n], bv1 = bias[n + 1];
            float ew0 = 0.f, ew1 = 0.f;
            if (EPI == 2) { ew0 = exW[(size_t)n * 257]; ew1 = exW[(size_t)(n + 1) * 257]; }
#pragma unroll
            for (int h = 0; h < 2; h++) {
                const int m = m0 + wm + im * 16 + g + h * 8;
                float v0 = acc[im][jn][h * 2 + 0] + bv0;
                float v1 = acc[im][jn][h * 2 + 1] + bv1;
                if (EPI == 2) {
                    const float ec = exCol[m];
                    v0 += ec * ew0; v1 += ec * ew1;
                }
                if (EPI == 2 || EPI == 3) { v0 = fmaxf(v0, 0.f); v1 = fmaxf(v1, 0.f); }
                const size_t off = (size_t)m * N + n;
                if (EPI != 2)
                    *reinterpret_cast<float2*>(Cf + off) = make_float2(v0, v1);
                if (EPI == 0 || EPI == 2) {
                    __half2 ph;
                    ph.x = __float2half(v0); ph.y = __float2half(v1);
                    *reinterpret_cast<__half2*>(Chi + off) = ph;
                }
            }
        }
    }
}

// ======================= gated final combine =======================
__global__ void __launch_bounds__(256) gatedfin_k(
    const float* __restrict__ part, const float* __restrict__ gb,
    float* __restrict__ Amat)
{
    int m = blockIdx.x * 256 + threadIdx.x;
    Amat[m] = part[m] + part[M_ + m] + part[2 * M_ + m] + part[3 * M_ + m] + gb[0];
}

// ======================= softmax over T + bag + At =======================
__global__ void __launch_bounds__(256) softbag_kernel(
    const float* __restrict__ Amat, const float* __restrict__ feat,
    float* __restrict__ bag, float* __restrict__ outAt)
{
    __shared__ float p[32];
    int b = blockIdx.x;
    int tid = threadIdx.x;
    if (tid < 32) {
        float v = Amat[b * 32 + tid];
        outAt[b * 32 + tid] = v;
        float mx = v;
#pragma unroll
        for (int o = 16; o; o >>= 1) mx = fmaxf(mx, __shfl_xor_sync(0xffffffffu, mx, o));
        float e = expf(v - mx);
        float s = e;
#pragma unroll
        for (int o = 16; o; o >>= 1) s += __shfl_xor_sync(0xffffffffu, s, o);
        p[tid] = e / s;
    }
    __syncthreads();
    float acc = 0.f;
#pragma unroll 8
    for (int t = 0; t < 32; t++) acc += p[t] * feat[(size_t)(b * 32 + t) * 256 + tid];
    bag[b * 256 + tid] = acc;
}

// ======================= bag classifier =======================
__global__ void __launch_bounds__(256) bagclf_kernel(
    const float* __restrict__ bag,
    const float* __restrict__ w0, const float* __restrict__ b0,
    const float* __restrict__ w1, const float* __restrict__ b1,
    const float* __restrict__ w2, const float* __restrict__ b2,
    const float* __restrict__ w3, const float* __restrict__ b3,
    float* __restrict__ outp)
{
    __shared__ float sb[8 * 256];
    __shared__ float sh[8 * 256];
    int base = blockIdx.x * 8;
    int tid = threadIdx.x;
#pragma unroll
    for (int i = 0; i < 8; i++) sb[tid + i * 256] = bag[(size_t)base * 256 + tid + i * 256];
    __syncthreads();
    {
        float acc[8] = {0, 0, 0, 0, 0, 0, 0, 0};
        const float* w = w0 + (size_t)tid * 256;
        for (int l = 0; l < 256; l++) {
            float wv = w[l];
#pragma unroll
            for (int r = 0; r < 8; r++) acc[r] += wv * sb[r * 256 + l];
        }
        float bb = b0[tid];
#pragma unroll
        for (int r = 0; r < 8; r++) sh[r * 256 + tid] = fmaxf(acc[r] + bb, 0.f);
    }
    __syncthreads();
    if (tid < 128) {
        float acc[8] = {0, 0, 0, 0, 0, 0, 0, 0};
        const float* w = w1 + (size_t)tid * 256;
        for (int l = 0; l < 256; l++) {
            float wv = w[l];
#pragma unroll
            for (int r = 0; r < 8; r++) acc[r] += wv * sh[r * 256 + l];
        }
        float bb = b1[tid];
#pragma unroll
        for (int r = 0; r < 8; r++) sb[r * 128 + tid] = fmaxf(acc[r] + bb, 0.f);
    }
    __syncthreads();
    if (tid < 32) {
        float acc[8] = {0, 0, 0, 0, 0, 0, 0, 0};
        const float* w = w2 + (size_t)tid * 128;
        for (int l = 0; l < 128; l++) {
            float wv = w[l];
#pragma unroll
            for (int r = 0; r < 8; r++) acc[r] += wv * sb[r * 128 + l];
        }
        float bb = b2[tid];
#pragma unroll
        for (int r = 0; r < 8; r++) sh[r * 32 + tid] = fmaxf(acc[r] + bb, 0.f);
    }
    __syncthreads();
    if (tid < 8) {
        float a = 0.f;
        for (int j = 0; j < 32; j++) a += w3[j] * sh[tid * 32 + j];
        float o1 = 1.f / (1.f + expf(-(a + b3[0])));
        outp[(size_t)(base + tid) * 2 + 0] = 0.5f * o1;
    }
}

// ======================= seg tail =======================
__global__ void __launch_bounds__(256) segtail_kernel(
    const float* __restrict__ h1,
    const float* __restrict__ w2, const float* __restrict__ b2,
    const float* __restrict__ w3, const float* __restrict__ b3,
    float* __restrict__ out_seg)
{
    __shared__ float sw2[128 * 32];
    __shared__ float sh1[8 * 128];
    int m0 = blockIdx.x * 8;
    int tid = threadIdx.x;
#pragma unroll
    for (int i = 0; i < 16; i++) {
        int idx = tid + i * 256;
        sw2[(idx & 127) * 32 + (idx >> 7)] = w2[idx];
    }
#pragma unroll
    for (int i = 0; i < 4; i++) {
        int idx = tid + i * 256;
        sh1[idx] = h1[(size_t)m0 * 128 + idx];
    }
    __syncthreads();
    int r = tid >> 5, j = tid & 31;
    float acc = b2[j];
#pragma unroll 8
    for (int l = 0; l < 128; l++) acc += sw2[l * 32 + j] * sh1[r * 128 + l];
    float h2 = fmaxf(acc, 0.f);
    float v = h2 * w3[j];
#pragma unroll
    for (int o = 16; o; o >>= 1) v += __shfl_xor_sync(0xffffffffu, v, o);
    if (j == 0) out_seg[m0 + r] = 1.f / (1.f + expf(-(v + b3[0])));
}

// ======================= per-sample 2-means v3 (2 syncs/iter, all-resident) =======
// 512 threads: warp w handles t = w and t = w+16. Norms computed redundantly per
// warp; mask computed redundantly per warp via ballot over shared sassign.
// Exact early exit on fixed points and period-2 cycles.
__global__ void __launch_bounds__(512, 4) kmeans_assign_k(
    const float* __restrict__ feat,
    float* __restrict__ out_assign, int* __restrict__ out_mask)
{
    __shared__ float sf[32 * 256];
    __shared__ float sc[2 * 256];
    __shared__ int sassign[32];
    int b = blockIdx.x;
    int tid = threadIdx.x;
    int lane = tid & 31, w = tid >> 5;   // w in 0..15

    {
        const float4* src = reinterpret_cast<const float4*>(feat + (size_t)b * 8192);
        float4* dst = reinterpret_cast<float4*>(sf);
#pragma unroll
        for (int i = 0; i < 4; i++) dst[tid + i * 512] = src[tid + i * 512];
    }
    __syncthreads();
    if (tid < 256) {
        sc[tid] = sf[tid];
        sc[256 + tid] = sf[4096 + tid];
    }
    __syncthreads();

    unsigned prev1 = 0, prev2 = 0, final_mask = 0;
    bool done = false;
    for (int it = 0; it < 100 && !done; it++) {
        // phase A: norms (redundant per warp) + dots for t=w, t=w+16
        float n0 = 0.f, n1 = 0.f, d0a = 0.f, d1a = 0.f, d0b = 0.f, d1b = 0.f;
#pragma unroll
        for (int i = 0; i < 8; i++) {
            int k = lane + i * 32;
            float c0 = sc[k], c1 = sc[256 + k];
            float fa = sf[w * 256 + k], fb = sf[(w + 16) * 256 + k];
            n0 += c0 * c0; n1 += c1 * c1;
            d0a += fa * c0; d1a += fa * c1;
            d0b += fb * c0; d1b += fb * c1;
        }
#pragma unroll
        for (int o = 16; o; o >>= 1) {
            n0  += __shfl_xor_sync(0xffffffffu, n0, o);
            n1  += __shfl_xor_sync(0xffffffffu, n1, o);
            d0a += __shfl_xor_sync(0xffffffffu, d0a, o);
            d1a += __shfl_xor_sync(0xffffffffu, d1a, o);
            d0b += __shfl_xor_sync(0xffffffffu, d0b, o);
            d1b += __shfl_xor_sync(0xffffffffu, d1b, o);
        }
        if (lane == 0) {
            float inv0 = 1.f / (sqrtf(n0) + 1e-8f);
            float inv1 = 1.f / (sqrtf(n1) + 1e-8f);
            sassign[w]      = (d1a * inv1 > d0a * inv0) ? 1 : 0;
            sassign[w + 16] = (d1b * inv1 > d0b * inv0) ? 1 : 0;
        }
        __syncthreads();
        // phase C: every warp computes mask redundantly; cycle check; center update
        unsigned mask = __ballot_sync(0xffffffffu, sassign[lane] != 0);
        if (it >= 1 && mask == prev1) { final_mask = mask; done = true; }
        else if (it >= 2 && mask == prev2) {
            final_mask = (((99 - it) & 1) == 0) ? mask : prev1;
            done = true;
        } else {
            prev2 = prev1; prev1 = mask; final_mask = mask;
            if (it == 99) done = true;
            else if (tid < 256) {
                int cnt1 = __popc(mask), cnt0 = 32 - cnt1;
                float a0 = 0.f, a1 = 0.f;
#pragma unroll
                for (int t = 0; t < 32; t++) {
                    float fv = sf[t * 256 + tid];
                    if ((mask >> t) & 1) a1 += fv; else a0 += fv;
                }
                if (cnt0 > 0) sc[tid] = a0 / (float)cnt0;
                if (cnt1 > 0) sc[256 + tid] = a1 / (float)cnt1;
            }
        }
        __syncthreads();
    }

    if (tid < 32) {
        out_assign[b * 32 + tid] = (float)((final_mask >> tid) & 1);
        if (tid == 0) out_mask[b] = (int)final_mask;
    }
}

// ======================= output2 join =======================
__global__ void __launch_bounds__(256) out2_k(
    const int* __restrict__ mask_arr, const float* __restrict__ seg,
    float* __restrict__ outp)
{
    int b = blockIdx.x * 8 + (threadIdx.x >> 5);
    int lane = threadIdx.x & 31;
    unsigned mask = (unsigned)mask_arr[b];
    float s = seg[b * 32 + lane];
    int bit = (mask >> lane) & 1;
    float v0 = bit ? 0.f : s;
    float v1 = bit ? s : 0.f;
#pragma unroll
    for (int o = 16; o; o >>= 1) {
        v0 += __shfl_xor_sync(0xffffffffu, v0, o);
        v1 += __shfl_xor_sync(0xffffffffu, v1, o);
    }
    if (lane == 0) {
        int cnt1 = __popc(mask);
        int cnt0 = 32 - cnt1;
        float m0 = (cnt0 > 0) ? v0 / (float)cnt0 : -INFINITY;
        float m1 = (cnt1 > 0) ? v1 / (float)cnt1 : -INFINITY;
        outp[(size_t)b * 2 + 1] = 0.5f * fmaxf(m0, m1);
    }
}

// ======================= launch =======================
extern "C" void kernel_launch(void* const* d_in, const int* in_sizes, int n_in,
                              void* d_out, int out_size)
{
    const float* x      = (const float*)d_in[0];
    const float* tsn_w  = (const float*)d_in[1];
    const float* tsn_b  = (const float*)d_in[2];
    const float* aV_w   = (const float*)d_in[3];
    const float* aV_b   = (const float*)d_in[4];
    const float* aU_w   = (const float*)d_in[5];
    const float* aU_b   = (const float*)d_in[6];
    const float* gate_w = (const float*)d_in[7];
    const float* gate_b = (const float*)d_in[8];
    const float* cb_w0 = (const float*)d_in[9],  *cb_b0 = (const float*)d_in[10];
    const float* cb_w1 = (const float*)d_in[11], *cb_b1 = (const float*)d_in[12];
    const float* cb_w2 = (const float*)d_in[13], *cb_b2 = (const float*)d_in[14];
    const float* cb_w3 = (const float*)d_in[15], *cb_b3 = (const float*)d_in[16];
    const float* cs_w0 = (const float*)d_in[17], *cs_b0 = (const float*)d_in[18];
    const float* cs_w1 = (const float*)d_in[19], *cs_b1 = (const float*)d_in[20];
    const float* cs_w2 = (const float*)d_in[21], *cs_b2 = (const float*)d_in[22];
    const float* cs_w3 = (const float*)d_in[23], *cs_b3 = (const float*)d_in[24];

    float* out = (float*)d_out;
    float* feat    = out + OFF_FEAT;
    float* oAssign = out + OFF_ASSIGN;
    float* oSeg    = out + OFF_SEG;
    float* oOut    = out + OFF_OUT;
    float* oAt     = out + OFF_AT;

    __half *xh, *wt, *bw, *fhi, *h0hi;
    float *part, *Amat, *bag, *h1;
    int* kmask;
    cudaGetSymbolAddress((void**)&xh, g_xh);
    cudaGetSymbolAddress((void**)&wt, g_wt);     cudaGetSymbolAddress((void**)&bw, g_bw);
    cudaGetSymbolAddress((void**)&fhi, g_fhi);   cudaGetSymbolAddress((void**)&h0hi, g_h0hi);
    cudaGetSymbolAddress((void**)&part, g_part);
    cudaGetSymbolAddress((void**)&Amat, g_Amat); cudaGetSymbolAddress((void**)&bag, g_bag);
    cudaGetSymbolAddress((void**)&h1, g_h1);
    cudaGetSymbolAddress((void**)&kmask, g_kmask);

    static cudaStream_t s1 = nullptr, s2 = nullptr;
    static cudaEvent_t evRoot, evX0, evX1, evWt, evW, evF0, evF1, evKm, evA, evSeg;
    if (s1 == nullptr) {
        cudaStreamCreateWithFlags(&s1, cudaStreamNonBlocking);
        cudaStreamCreateWithFlags(&s2, cudaStreamNonBlocking);
        cudaEventCreateWithFlags(&evRoot, cudaEventDisableTiming);
        cudaEventCreateWithFlags(&evX0,   cudaEventDisableTiming);
        cudaEventCreateWithFlags(&evX1,   cudaEventDisableTiming);
        cudaEventCreateWithFlags(&evWt,   cudaEventDisableTiming);
        cudaEventCreateWithFlags(&evW,    cudaEventDisableTiming);
        cudaEventCreateWithFlags(&evF0,   cudaEventDisableTiming);
        cudaEventCreateWithFlags(&evF1,   cudaEventDisableTiming);
        cudaEventCreateWithFlags(&evKm,   cudaEventDisableTiming);
        cudaEventCreateWithFlags(&evA,    cudaEventDisableTiming);
        cudaEventCreateWithFlags(&evSeg,  cudaEventDisableTiming);
    }

    const int SMB1 = 3 * 32768;   // conv: TP=0, S=3
    const int SMB0 = 2 * 32768;   // small GEMMs: TP=0, S=2
    cudaFuncSetAttribute(mm_gemm<1, 0, 0, 3>, cudaFuncAttributeMaxDynamicSharedMemorySize, SMB1);
    cudaFuncSetAttribute(mm_gemm<0, 5, 0, 2>, cudaFuncAttributeMaxDynamicSharedMemorySize, SMB0);
    cudaFuncSetAttribute(mm_gemm<0, 2, 0, 2>, cudaFuncAttributeMaxDynamicSharedMemorySize, SMB0);
    cudaFuncSetAttribute(mm_gemm<0, 3, 0, 2>, cudaFuncAttributeMaxDynamicSharedMemorySize, SMB0);

    // fork points
    cudaEventRecord(evRoot, 0);
    cudaStreamWaitEvent(s1, evRoot, 0);
    cudaStreamWaitEvent(s2, evRoot, 0);

    // #1: x half0 (main); #2: x half1 (s2); #3: conv weights (s1)
    conv_x_k<<<32768, 256>>>((const float4*)x, (__half2*)xh);
    cudaEventRecord(evX0, 0);
    conv_x_k<<<32768, 256, 0, s2>>>((const float4*)x + 8388608, (__half2*)(xh + 33554432));
    cudaEventRecord(evX1, s2);
    splitw_conv_k<<<(L_ * KCONV) / 256, 256, 0, s1>>>(tsn_w, wt);
    cudaEventRecord(evWt, s1);

    // #4: conv half0 (main; waits weights + other half's x)  [PROFILED]
    cudaStreamWaitEvent(0, evWt, 0);
    cudaStreamWaitEvent(0, evX1, 0);
    mm_gemm<1, 0, 0, 3><<<dim3(2, 64), 256, SMB1>>>(xh, nullptr, FIN, wt, KCONV,
                                                    tsn_b, nullptr, nullptr,
                                                    feat, fhi, 256, KCONV, 0);
    cudaEventRecord(evF0, 0);

    // conv half1 (s2; waits weights + half0's x)
    cudaStreamWaitEvent(s2, evWt, 0);
    cudaStreamWaitEvent(s2, evX0, 0);
    mm_gemm<1, 0, 0, 3><<<dim3(2, 64), 256, SMB1, s2>>>(xh, nullptr, FIN, wt, KCONV,
                                                        tsn_b, nullptr, nullptr,
                                                        feat, fhi, 256, KCONV, 8192);
    cudaEventRecord(evF1, s2);

    // remaining weight repacks on s1 (overlap conv)
    splitw_pair_k<<<512, 256, 0, s1>>>(aV_w, aU_w, bw);
    splitw_gen_k<<<256, 256, 0, s1>>>(cs_w0, 257, 65536, bw + 131072);
    splitw_gen_k<<<128, 256, 0, s1>>>(cs_w1, 256, 32768, bw + 196608);
    cudaEventRecord(evW, s1);

    // kmeans on s2 after full feat (512 threads, all blocks resident)
    cudaStreamWaitEvent(s2, evF0, 0);
    kmeans_assign_k<<<B_, 512, 0, s2>>>(feat, oAssign, kmask);
    cudaEventRecord(evKm, s2);

    // main chain: fused aVU+gated (EPI5, 1-pass) -> partials -> Amat
    cudaStreamWaitEvent(0, evF1, 0);
    cudaStreamWaitEvent(0, evW, 0);
    mm_gemm<0, 5, 0, 2><<<dim3(4, 128), 256, SMB0>>>(fhi, nullptr, 256, bw, 256,
                                                     aV_b, aU_b, gate_w,
                                                     part, nullptr, 512, 256, 0);
    gatedfin_k<<<M_ / 256, 256>>>(part, gate_b, Amat);
    cudaEventRecord(evA, 0);

    // seg chain on s1 (parallel with softbag/bagclf), all 1-pass
    cudaStreamWaitEvent(s1, evA, 0);
    mm_gemm<0, 2, 0, 2><<<dim3(2, 128), 256, SMB0, s1>>>(fhi, nullptr, 256, bw + 131072, 256,
                                                         cs_b0, Amat, cs_w0 + 256,
                                                         nullptr, h0hi, 256, 256, 0);
    mm_gemm<0, 3, 0, 2><<<dim3(1, 128), 256, SMB0, s1>>>(h0hi, nullptr, 256, bw + 196608, 256,
                                                         cs_b1, nullptr, nullptr,
                                                         h1, nullptr, 128, 256, 0);
    segtail_kernel<<<M_ / 8, 256, 0, s1>>>(h1, cs_w2, cs_b2, cs_w3, cs_b3, oSeg);
    cudaEventRecord(evSeg, s1);

    // bag chain on main stream
    softbag_kernel<<<B_, 256>>>(Amat, feat, bag, oAt);
    bagclf_kernel<<<B_ / 8, 256>>>(bag, cb_w0, cb_b0, cb_w1, cb_b1,
                                   cb_w2, cb_b2, cb_w3, cb_b3, oOut);

    // join: output2 needs seg + kmeans masks
    cudaStreamWaitEvent(0, evSeg, 0);
    cudaStreamWaitEvent(0, evKm, 0);
    out2_k<<<B_ / 8, 256>>>(kmask, oSeg, oOut);
}

// round 13
// speedup vs baseline: 1.2268x; 1.1133x over previous
#include <cuda_runtime.h>
#include <cuda_fp16.h>
#include <math.h>
#include <stdint.h>

#define B_   512
#define T_   32
#define FIN  4096
#define L_   256
#define M_   (B_*T_)
#define KCONV (3*FIN)

#define OFF_FEAT   0
#define OFF_ASSIGN 4194304
#define OFF_SEG    4210688
#define OFF_OUT    4227072
#define OFF_AT     4228096

// -------- scratch (device globals) --------
__device__ __align__(16) __half g_xh[(size_t)M_ * FIN];      // x fp16
__device__ __align__(16) __half g_wt[(size_t)L_ * KCONV];    // conv weight fp16 [n][k]
__device__ __align__(16) __half g_bw[229376];                // aVU(paired)|cs0|cs1 fp16
__device__ __align__(16) __half g_fhi[(size_t)M_ * L_];      // feature fp16
__device__ __align__(16) __half g_h0hi[(size_t)M_ * 256];    // seg hidden fp16
__device__ float g_part[4 * M_];
__device__ float g_Amat[M_];
__device__ float g_bag[B_ * L_];
__device__ float g_h1[(size_t)M_ * 128];
__device__ int   g_kmask[B_];

// ======================= helpers =======================
__device__ __forceinline__ uint32_t smem_u32(const void* p) {
    uint32_t a;
    asm("{ .reg .u64 t; cvta.to.shared.u64 t, %1; cvt.u32.u64 %0, t; }" : "=r"(a) : "l"(p));
    return a;
}
__device__ __forceinline__ void cp16(uint32_t dst, const void* src, uint32_t sz) {
    asm volatile("cp.async.cg.shared.global [%0], [%1], 16, %2;"
                 :: "r"(dst), "l"(src), "r"(sz) : "memory");
}
__device__ __forceinline__ void ldm4(uint32_t* r, uint32_t addr) {
    asm volatile("ldmatrix.sync.aligned.m8n8.x4.shared.b16 {%0,%1,%2,%3}, [%4];"
                 : "=r"(r[0]), "=r"(r[1]), "=r"(r[2]), "=r"(r[3]) : "r"(addr));
}
__device__ __forceinline__ void mma16816(float* c, const uint32_t* a, const uint32_t* b) {
    asm volatile("mma.sync.aligned.m16n8k16.row.col.f32.f16.f16.f32 "
                 "{%0,%1,%2,%3}, {%4,%5,%6,%7}, {%8,%9}, {%0,%1,%2,%3};"
                 : "+f"(c[0]), "+f"(c[1]), "+f"(c[2]), "+f"(c[3])
                 : "r"(a[0]), "r"(a[1]), "r"(a[2]), "r"(a[3]), "r"(b[0]), "r"(b[1]));
}
__device__ __forceinline__ float tanh_fast(float x) {
    float r;
    asm("tanh.approx.f32 %0, %1;" : "=f"(r) : "f"(x));
    return r;
}
__device__ __forceinline__ float sigmoid_fast(float x) {
    return __fdividef(1.f, 1.f + __expf(-x));
}

// ======================= convert / repack kernels =======================
__global__ void conv_x_k(const float4* __restrict__ x, __half2* __restrict__ o) {
    size_t i = (size_t)blockIdx.x * 256 + threadIdx.x;
    float4 v = x[i];
    __half2 a, b;
    a.x = __float2half(v.x); a.y = __float2half(v.y);
    b.x = __float2half(v.z); b.y = __float2half(v.w);
    o[2 * i] = a; o[2 * i + 1] = b;
}

__global__ void splitw_conv_k(const float* __restrict__ w, __half* __restrict__ o) {
    int idx = blockIdx.x * 256 + threadIdx.x;          // [n][k], k = tap*4096 + c
    int n = idx / KCONV;
    int k = idx - n * KCONV;
    int tap = k >> 12, c = k & 4095;
    o[idx] = __float2half(w[(size_t)n * KCONV + c * 3 + tap]);
}

// pair-interleaved: row n even -> aV_w[n/2], odd -> aU_w[n/2]
__global__ void splitw_pair_k(const float* __restrict__ wa, const float* __restrict__ wb,
                              __half* __restrict__ o) {
    int idx = blockIdx.x * 256 + threadIdx.x;
    int n = idx >> 8, k = idx & 255;
    const float* w = (n & 1) ? wb : wa;
    o[idx] = __float2half(w[(size_t)(n >> 1) * 256 + k]);
}

__global__ void splitw_gen_k(const float* __restrict__ w, int srcStride, int total,
                             __half* __restrict__ o) {
    int idx = blockIdx.x * 256 + threadIdx.x;
    if (idx >= total) return;
    int n = idx >> 8, k = idx & 255;
    o[idx] = __float2half(w[(size_t)n * srcStride + k]);
}

// ======================= conv GEMM: CTA 128x256, warp tile 64x64 =======================
// 8 warps = 2(m) x 4(n). LDSM/MMA = 0.25 (vs 0.375) -> -33% L1 traffic.
// Accumulation order per element identical to previous version (chunk x ks order).
template<int S>
__global__ void __launch_bounds__(256) conv_gemm(
    const __half* __restrict__ A, const __half* __restrict__ Bw,
    const float* __restrict__ bias,
    float* __restrict__ Cf, __half* __restrict__ Chi)
{
    constexpr uint32_t STG = 49152u;   // A 16KB + B 32KB
    constexpr uint32_t BOFF = 16384u;
    extern __shared__ __align__(128) char smem[];
    const int tid = threadIdx.x;
    const int m0 = blockIdx.x * 128;
    const uint32_t sb = smem_u32(smem);
    const int NCH = KCONV >> 6;        // 192

    const int lane = tid & 31, warp = tid >> 5;
    const int wm = (warp >> 2) * 64, wn = (warp & 3) * 64;
    const int rsel = lane & 15, ksel = lane >> 4;

    float acc[4][8][4];
#pragma unroll
    for (int i = 0; i < 4; i++)
#pragma unroll
        for (int j = 0; j < 8; j++)
#pragma unroll
            for (int u = 0; u < 4; u++) acc[i][j][u] = 0.f;

    auto issue_load = [&](int ch) {
        const uint32_t slot = (uint32_t)(ch % S);
        const int k0 = ch << 6;
        if (tid < 128) {
            const int tap = k0 >> 12;
            const int coff = k0 & 4095;
            long sr = (long)m0 + tid + tap - 1;
            uint32_t sz = 16;
            const int tt = (tid & 31) + tap - 1;
            if (tt < 0 || tt > 31) { sz = 0; sr = m0 + tid; }
            const __half* src = A + sr * FIN + coff;
            const uint32_t d = sb + slot * STG + tid * 128;
            const int xm = tid & 7;
#pragma unroll
            for (int c = 0; c < 8; c++)
                cp16(d + (uint32_t)((c ^ xm) << 4), src + c * 8, sz);
        } else {
            const int r = tid - 128;
#pragma unroll
            for (int q = 0; q < 2; q++) {
                const int row = r + q * 128;
                const __half* src = Bw + (size_t)row * KCONV + k0;
                const uint32_t d = sb + slot * STG + BOFF + row * 128;
                const int xm = row & 7;
#pragma unroll
                for (int c = 0; c < 8; c++)
                    cp16(d + (uint32_t)((c ^ xm) << 4), src + c * 8, 16);
            }
        }
        asm volatile("cp.async.commit_group;" ::: "memory");
    };

#pragma unroll
    for (int i = 0; i < S - 1; i++) issue_load(i);

    for (int ch = 0; ch < NCH; ch++) {
        if (ch + S - 2 < NCH - 1)
            asm volatile("cp.async.wait_group %0;" :: "n"(S - 2) : "memory");
        else
            asm volatile("cp.async.wait_group 0;" ::: "memory");
        __syncthreads();
        if (ch + S - 1 < NCH) issue_load(ch + S - 1);

        const uint32_t base = sb + (uint32_t)(ch % S) * STG;
#pragma unroll
        for (int ks = 0; ks < 4; ks++) {
            const int kc = ks * 2 + ksel;
            uint32_t ah[4][4];
#pragma unroll
            for (int im = 0; im < 4; im++) {
                const int row = wm + im * 16 + rsel;
                const uint32_t a = base + row * 128 + (uint32_t)(((kc ^ (row & 7))) << 4);
                ldm4(ah[im], a);
            }
            uint32_t bh[8][2];
#pragma unroll
            for (int j2 = 0; j2 < 4; j2++) {
                const int row = wn + j2 * 16 + rsel;
                const uint32_t a = base + BOFF + row * 128 + (uint32_t)(((kc ^ (row & 7))) << 4);
                uint32_t t[4];
                ldm4(t, a);
                bh[j2 * 2][0] = t[0]; bh[j2 * 2][1] = t[2];
                bh[j2 * 2 + 1][0] = t[1]; bh[j2 * 2 + 1][1] = t[3];
            }
#pragma unroll
            for (int im = 0; im < 4; im++)
#pragma unroll
                for (int jn = 0; jn < 8; jn++)
                    mma16816(acc[im][jn], ah[im], bh[jn]);
        }
    }

    // ---- epilogue: bias, write fp32 + fp16 ----
    const int g = lane >> 2, t4 = lane & 3;
#pragma unroll
    for (int im = 0; im < 4; im++) {
#pragma unroll
        for (int jn = 0; jn < 8; jn++) {
            const int n = wn + jn * 8 + t4 * 2;
            const float bv0 = bias[n], bv1 = bias[n + 1];
#pragma unroll
            for (int h = 0; h < 2; h++) {
                const int m = m0 + wm + im * 16 + g + h * 8;
                float v0 = acc[im][jn][h * 2 + 0] + bv0;
                float v1 = acc[im][jn][h * 2 + 1] + bv1;
                const size_t off = (size_t)m * 256 + n;
                *reinterpret_cast<float2*>(Cf + off) = make_float2(v0, v1);
                __half2 ph;
                ph.x = __float2half(v0); ph.y = __float2half(v1);
                *reinterpret_cast<__half2*>(Chi + off) = ph;
            }
        }
    }
}

// ======================= small HMMA GEMM (unchanged from R12) =======================
template<int EPI, int S>
__global__ void __launch_bounds__(256, 2) mm_gemm(
    const __half* __restrict__ Ahi, int ldA,
    const __half* __restrict__ Bw, int ldB,
    const float* __restrict__ bias, const float* __restrict__ exCol,
    const float* __restrict__ exW,
    float* __restrict__ Cf, __half* __restrict__ Chi,
    int N, int K)
{
    constexpr uint32_t STG  = 32768u;
    constexpr uint32_t BOFF = 16384u;
    extern __shared__ __align__(128) char smem[];
    const int tid = threadIdx.x;
    const int m0 = blockIdx.y * 128;
    const int n0 = blockIdx.x * 128;
    const uint32_t sb = smem_u32(smem);
    const int NCH = K >> 6;

    const int lane = tid & 31, warp = tid >> 5;
    const int wm = (warp >> 2) * 64, wn = (warp & 3) * 32;
    const int rsel = lane & 15, ksel = lane >> 4;

    float acc[4][4][4];
#pragma unroll
    for (int i = 0; i < 4; i++)
#pragma unroll
        for (int j = 0; j < 4; j++)
#pragma unroll
            for (int u = 0; u < 4; u++) acc[i][j][u] = 0.f;

    auto issue_load = [&](int ch) {
        const uint32_t slot = (uint32_t)(ch % S);
        const int k0 = ch << 6;
        if (tid < 128) {
            const __half* src = Ahi + (size_t)(m0 + tid) * ldA + k0;
            const uint32_t d = sb + slot * STG + tid * 128;
            const int xm = tid & 7;
#pragma unroll
            for (int c = 0; c < 8; c++)
                cp16(d + (uint32_t)((c ^ xm) << 4), src + c * 8, 16);
        } else {
            const int row = tid - 128;
            const __half* src = Bw + (size_t)(n0 + row) * ldB + k0;
            const uint32_t d = sb + slot * STG + BOFF + row * 128;
            const int xm = row & 7;
#pragma unroll
            for (int c = 0; c < 8; c++)
                cp16(d + (uint32_t)((c ^ xm) << 4), src + c * 8, 16);
        }
        asm volatile("cp.async.commit_group;" ::: "memory");
    };

#pragma unroll
    for (int i = 0; i < S - 1; i++) issue_load(i);

    for (int ch = 0; ch < NCH; ch++) {
        if (ch + S - 2 < NCH - 1)
            asm volatile("cp.async.wait_group %0;" :: "n"(S - 2) : "memory");
        else
            asm volatile("cp.async.wait_group 0;" ::: "memory");
        __syncthreads();
        if (ch + S - 1 < NCH) issue_load(ch + S - 1);

        const uint32_t base = sb + (uint32_t)(ch % S) * STG;
#pragma unroll
        for (int ks = 0; ks < 4; ks++) {
            const int kc = ks * 2 + ksel;
            uint32_t ah[4][4];
#pragma unroll
            for (int im = 0; im < 4; im++) {
                const int row = wm + im * 16 + rsel;
                const uint32_t a = base + row * 128 + (uint32_t)(((kc ^ (row & 7))) << 4);
                ldm4(ah[im], a);
            }
            uint32_t bh[4][2];
#pragma unroll
            for (int j2 = 0; j2 < 2; j2++) {
                const int row = wn + j2 * 16 + rsel;
                const uint32_t a = base + BOFF + row * 128 + (uint32_t)(((kc ^ (row & 7))) << 4);
                uint32_t t[4];
                ldm4(t, a);
                bh[j2 * 2][0] = t[0]; bh[j2 * 2][1] = t[2];
                bh[j2 * 2 + 1][0] = t[1]; bh[j2 * 2 + 1][1] = t[3];
            }
#pragma unroll
            for (int im = 0; im < 4; im++)
#pragma unroll
                for (int jn = 0; jn < 4; jn++)
                    mma16816(acc[im][jn], ah[im], bh[jn]);
        }
    }

    const int g = lane >> 2, t4 = lane & 3;

    if (EPI == 5) {
        float part[4][2];
#pragma unroll
        for (int im = 0; im < 4; im++)
#pragma unroll
            for (int h = 0; h < 2; h++) {
                float p = 0.f;
#pragma unroll
                for (int jn = 0; jn < 4; jn++) {
                    const int n = n0 + wn + jn * 8 + t4 * 2;
                    const int d = n >> 1;
                    float v = acc[im][jn][h * 2 + 0] + bias[d];
                    float u = acc[im][jn][h * 2 + 1] + exCol[d];
                    p += tanh_fast(v) * sigmoid_fast(u) * exW[d];
                }
                p += __shfl_xor_sync(0xffffffffu, p, 1);
                p += __shfl_xor_sync(0xffffffffu, p, 2);
                part[im][h] = p;
            }
        __syncthreads();
        float* sred = reinterpret_cast<float*>(smem);
        if (t4 == 0) {
#pragma unroll
            for (int im = 0; im < 4; im++)
#pragma unroll
                for (int h = 0; h < 2; h++) {
                    const int lm = wm + im * 16 + g + h * 8;
                    sred[(warp & 3) * 128 + lm] = part[im][h];
                }
        }
        __syncthreads();
        if (tid < 128) {
            float s = sred[tid] + sred[128 + tid] + sred[256 + tid] + sred[384 + tid];
            Cf[(size_t)blockIdx.x * M_ + m0 + tid] = s;
        }
        return;
    }

#pragma unroll
    for (int im = 0; im < 4; im++) {
#pragma unroll
        for (int jn = 0; jn < 4; jn++) {
            const int n = n0 + wn + jn * 8 + t4 * 2;
            const float bv0 = bias[n], bv1 = bias[n + 1];
            float ew0 = 0.f, ew1 = 0.f;
            if (EPI == 2) { ew0 = exW[(size_t)n * 257]; ew1 = exW[(size_t)(n + 1) * 257]; }
#pragma unroll
            for (int h = 0; h < 2; h++) {
                const int m = m0 + wm + im * 16 + g + h * 8;
                float v0 = acc[im][jn][h * 2 + 0] + bv0;
                float v1 = acc[im][jn][h * 2 + 1] + bv1;
                if (EPI == 2) {
                    const float ec = exCol[m];
                    v0 += ec * ew0; v1 += ec * ew1;
                }
                if (EPI == 2 || EPI == 3) { v0 = fmaxf(v0, 0.f); v1 = fmaxf(v1, 0.f); }
                const size_t off = (size_t)m * N + n;
                if (EPI != 2)
                    *reinterpret_cast<float2*>(Cf + off) = make_float2(v0, v1);
                if (EPI == 2) {
                    __half2 ph;
                    ph.x = __float2half(v0); ph.y = __float2half(v1);
                    *reinterpret_cast<__half2*>(Chi + off) = ph;
                }
            }
        }
    }
}

// ======================= gated final combine =======================
__global__ void __launch_bounds__(256) gatedfin_k(
    const float* __restrict__ part, const float* __restrict__ gb,
    float* __restrict__ Amat)
{
    int m = blockIdx.x * 256 + threadIdx.x;
    Amat[m] = part[m] + part[M_ + m] + part[2 * M_ + m] + part[3 * M_ + m] + gb[0];
}

// ======================= softmax over T + bag + At =======================
__global__ void __launch_bounds__(256) softbag_kernel(
    const float* __restrict__ Amat, const float* __restrict__ feat,
    float* __restrict__ bag, float* __restrict__ outAt)
{
    __shared__ float p[32];
    int b = blockIdx.x;
    int tid = threadIdx.x;
    if (tid < 32) {
        float v = Amat[b * 32 + tid];
        outAt[b * 32 + tid] = v;
        float mx = v;
#pragma unroll
        for (int o = 16; o; o >>= 1) mx = fmaxf(mx, __shfl_xor_sync(0xffffffffu, mx, o));
        float e = expf(v - mx);
        float s = e;
#pragma unroll
        for (int o = 16; o; o >>= 1) s += __shfl_xor_sync(0xffffffffu, s, o);
        p[tid] = e / s;
    }
    __syncthreads();
    float acc = 0.f;
#pragma unroll 8
    for (int t = 0; t < 32; t++) acc += p[t] * feat[(size_t)(b * 32 + t) * 256 + tid];
    bag[b * 256 + tid] = acc;
}

// ======================= bag classifier =======================
__global__ void __launch_bounds__(256) bagclf_kernel(
    const float* __restrict__ bag,
    const float* __restrict__ w0, const float* __restrict__ b0,
    const float* __restrict__ w1, const float* __restrict__ b1,
    const float* __restrict__ w2, const float* __restrict__ b2,
    const float* __restrict__ w3, const float* __restrict__ b3,
    float* __restrict__ outp)
{
    __shared__ float sb[8 * 256];
    __shared__ float sh[8 * 256];
    int base = blockIdx.x * 8;
    int tid = threadIdx.x;
#pragma unroll
    for (int i = 0; i < 8; i++) sb[tid + i * 256] = bag[(size_t)base * 256 + tid + i * 256];
    __syncthreads();
    {
        float acc[8] = {0, 0, 0, 0, 0, 0, 0, 0};
        const float* w = w0 + (size_t)tid * 256;
        for (int l = 0; l < 256; l++) {
            float wv = w[l];
#pragma unroll
            for (int r = 0; r < 8; r++) acc[r] += wv * sb[r * 256 + l];
        }
        float bb = b0[tid];
#pragma unroll
        for (int r = 0; r < 8; r++) sh[r * 256 + tid] = fmaxf(acc[r] + bb, 0.f);
    }
    __syncthreads();
    if (tid < 128) {
        float acc[8] = {0, 0, 0, 0, 0, 0, 0, 0};
        const float* w = w1 + (size_t)tid * 256;
        for (int l = 0; l < 256; l++) {
            float wv = w[l];
#pragma unroll
            for (int r = 0; r < 8; r++) acc[r] += wv * sh[r * 256 + l];
        }
        float bb = b1[tid];
#pragma unroll
        for (int r = 0; r < 8; r++) sb[r * 128 + tid] = fmaxf(acc[r] + bb, 0.f);
    }
    __syncthreads();
    if (tid < 32) {
        float acc[8] = {0, 0, 0, 0, 0, 0, 0, 0};
        const float* w = w2 + (size_t)tid * 128;
        for (int l = 0; l < 128; l++) {
            float wv = w[l];
#pragma unroll
            for (int r = 0; r < 8; r++) acc[r] += wv * sb[r * 128 + l];
        }
        float bb = b2[tid];
#pragma unroll
        for (int r = 0; r < 8; r++) sh[r * 32 + tid] = fmaxf(acc[r] + bb, 0.f);
    }
    __syncthreads();
    if (tid < 8) {
        float a = 0.f;
        for (int j = 0; j < 32; j++) a += w3[j] * sh[tid * 32 + j];
        float o1 = 1.f / (1.f + expf(-(a + b3[0])));
        outp[(size_t)(base + tid) * 2 + 0] = 0.5f * o1;
    }
}

// ======================= seg tail =======================
__global__ void __launch_bounds__(256) segtail_kernel(
    const float* __restrict__ h1,
    const float* __restrict__ w2, const float* __restrict__ b2,
    const float* __restrict__ w3, const float* __restrict__ b3,
    float* __restrict__ out_seg)
{
    __shared__ float sw2[128 * 32];
    __shared__ float sh1[8 * 128];
    int m0 = blockIdx.x * 8;
    int tid = threadIdx.x;
#pragma unroll
    for (int i = 0; i < 16; i++) {
        int idx = tid + i * 256;
        sw2[(idx & 127) * 32 + (idx >> 7)] = w2[idx];
    }
#pragma unroll
    for (int i = 0; i < 4; i++) {
        int idx = tid + i * 256;
        sh1[idx] = h1[(size_t)m0 * 128 + idx];
    }
    __syncthreads();
    int r = tid >> 5, j = tid & 31;
    float acc = b2[j];
#pragma unroll 8
    for (int l = 0; l < 128; l++) acc += sw2[l * 32 + j] * sh1[r * 128 + l];
    float h2 = fmaxf(acc, 0.f);
    float v = h2 * w3[j];
#pragma unroll
    for (int o = 16; o; o >>= 1) v += __shfl_xor_sync(0xffffffffu, v, o);
    if (j == 0) out_seg[m0 + r] = 1.f / (1.f + expf(-(v + b3[0])));
}

// ======================= per-sample 2-means v3 (unchanged) =======================
__global__ void __launch_bounds__(512, 4) kmeans_assign_k(
    const float* __restrict__ feat,
    float* __restrict__ out_assign, int* __restrict__ out_mask)
{
    __shared__ float sf[32 * 256];
    __shared__ float sc[2 * 256];
    __shared__ int sassign[32];
    int b = blockIdx.x;
    int tid = threadIdx.x;
    int lane = tid & 31, w = tid >> 5;

    {
        const float4* src = reinterpret_cast<const float4*>(feat + (size_t)b * 8192);
        float4* dst = reinterpret_cast<float4*>(sf);
#pragma unroll
        for (int i = 0; i < 4; i++) dst[tid + i * 512] = src[tid + i * 512];
    }
    __syncthreads();
    if (tid < 256) {
        sc[tid] = sf[tid];
        sc[256 + tid] = sf[4096 + tid];
    }
    __syncthreads();

    unsigned prev1 = 0, prev2 = 0, final_mask = 0;
    bool done = false;
    for (int it = 0; it < 100 && !done; it++) {
        float n0 = 0.f, n1 = 0.f, d0a = 0.f, d1a = 0.f, d0b = 0.f, d1b = 0.f;
#pragma unroll
        for (int i = 0; i < 8; i++) {
            int k = lane + i * 32;
            float c0 = sc[k], c1 = sc[256 + k];
            float fa = sf[w * 256 + k], fb = sf[(w + 16) * 256 + k];
            n0 += c0 * c0; n1 += c1 * c1;
            d0a += fa * c0; d1a += fa * c1;
            d0b += fb * c0; d1b += fb * c1;
        }
#pragma unroll
        for (int o = 16; o; o >>= 1) {
            n0  += __shfl_xor_sync(0xffffffffu, n0, o);
            n1  += __shfl_xor_sync(0xffffffffu, n1, o);
            d0a += __shfl_xor_sync(0xffffffffu, d0a, o);
            d1a += __shfl_xor_sync(0xffffffffu, d1a, o);
            d0b += __shfl_xor_sync(0xffffffffu, d0b, o);
            d1b += __shfl_xor_sync(0xffffffffu, d1b, o);
        }
        if (lane == 0) {
            float inv0 = 1.f / (sqrtf(n0) + 1e-8f);
            float inv1 = 1.f / (sqrtf(n1) + 1e-8f);
            sassign[w]      = (d1a * inv1 > d0a * inv0) ? 1 : 0;
            sassign[w + 16] = (d1b * inv1 > d0b * inv0) ? 1 : 0;
        }
        __syncthreads();
        unsigned mask = __ballot_sync(0xffffffffu, sassign[lane] != 0);
        if (it >= 1 && mask == prev1) { final_mask = mask; done = true; }
        else if (it >= 2 && mask == prev2) {
            final_mask = (((99 - it) & 1) == 0) ? mask : prev1;
            done = true;
        } else {
            prev2 = prev1; prev1 = mask; final_mask = mask;
            if (it == 99) done = true;
            else if (tid < 256) {
                int cnt1 = __popc(mask), cnt0 = 32 - cnt1;
                float a0 = 0.f, a1 = 0.f;
#pragma unroll
                for (int t = 0; t < 32; t++) {
                    float fv = sf[t * 256 + tid];
                    if ((mask >> t) & 1) a1 += fv; else a0 += fv;
                }
                if (cnt0 > 0) sc[tid] = a0 / (float)cnt0;
                if (cnt1 > 0) sc[256 + tid] = a1 / (float)cnt1;
            }
        }
        __syncthreads();
    }

    if (tid < 32) {
        out_assign[b * 32 + tid] = (float)((final_mask >> tid) & 1);
        if (tid == 0) out_mask[b] = (int)final_mask;
    }
}

// ======================= output2 join =======================
__global__ void __launch_bounds__(256) out2_k(
    const int* __restrict__ mask_arr, const float* __restrict__ seg,
    float* __restrict__ outp)
{
    int b = blockIdx.x * 8 + (threadIdx.x >> 5);
    int lane = threadIdx.x & 31;
    unsigned mask = (unsigned)mask_arr[b];
    float s = seg[b * 32 + lane];
    int bit = (mask >> lane) & 1;
    float v0 = bit ? 0.f : s;
    float v1 = bit ? s : 0.f;
#pragma unroll
    for (int o = 16; o; o >>= 1) {
        v0 += __shfl_xor_sync(0xffffffffu, v0, o);
        v1 += __shfl_xor_sync(0xffffffffu, v1, o);
    }
    if (lane == 0) {
        int cnt1 = __popc(mask);
        int cnt0 = 32 - cnt1;
        float m0 = (cnt0 > 0) ? v0 / (float)cnt0 : -INFINITY;
        float m1 = (cnt1 > 0) ? v1 / (float)cnt1 : -INFINITY;
        outp[(size_t)b * 2 + 1] = 0.5f * fmaxf(m0, m1);
    }
}

// ======================= launch =======================
extern "C" void kernel_launch(void* const* d_in, const int* in_sizes, int n_in,
                              void* d_out, int out_size)
{
    const float* x      = (const float*)d_in[0];
    const float* tsn_w  = (const float*)d_in[1];
    const float* tsn_b  = (const float*)d_in[2];
    const float* aV_w   = (const float*)d_in[3];
    const float* aV_b   = (const float*)d_in[4];
    const float* aU_w   = (const float*)d_in[5];
    const float* aU_b   = (const float*)d_in[6];
    const float* gate_w = (const float*)d_in[7];
    const float* gate_b = (const float*)d_in[8];
    const float* cb_w0 = (const float*)d_in[9],  *cb_b0 = (const float*)d_in[10];
    const float* cb_w1 = (const float*)d_in[11], *cb_b1 = (const float*)d_in[12];
    const float* cb_w2 = (const float*)d_in[13], *cb_b2 = (const float*)d_in[14];
    const float* cb_w3 = (const float*)d_in[15], *cb_b3 = (const float*)d_in[16];
    const float* cs_w0 = (const float*)d_in[17], *cs_b0 = (const float*)d_in[18];
    const float* cs_w1 = (const float*)d_in[19], *cs_b1 = (const float*)d_in[20];
    const float* cs_w2 = (const float*)d_in[21], *cs_b2 = (const float*)d_in[22];
    const float* cs_w3 = (const float*)d_in[23], *cs_b3 = (const float*)d_in[24];

    float* out = (float*)d_out;
    float* feat    = out + OFF_FEAT;
    float* oAssign = out + OFF_ASSIGN;
    float* oSeg    = out + OFF_SEG;
    float* oOut    = out + OFF_OUT;
    float* oAt     = out + OFF_AT;

    __half *xh, *wt, *bw, *fhi, *h0hi;
    float *part, *Amat, *bag, *h1;
    int* kmask;
    cudaGetSymbolAddress((void**)&xh, g_xh);
    cudaGetSymbolAddress((void**)&wt, g_wt);     cudaGetSymbolAddress((void**)&bw, g_bw);
    cudaGetSymbolAddress((void**)&fhi, g_fhi);   cudaGetSymbolAddress((void**)&h0hi, g_h0hi);
    cudaGetSymbolAddress((void**)&part, g_part);
    cudaGetSymbolAddress((void**)&Amat, g_Amat); cudaGetSymbolAddress((void**)&bag, g_bag);
    cudaGetSymbolAddress((void**)&h1, g_h1);
    cudaGetSymbolAddress((void**)&kmask, g_kmask);

    static cudaStream_t s1 = nullptr, s2 = nullptr;
    static cudaEvent_t evRoot, evX1, evWt, evW, evF, evKm, evA, evSeg;
    if (s1 == nullptr) {
        cudaStreamCreateWithFlags(&s1, cudaStreamNonBlocking);
        cudaStreamCreateWithFlags(&s2, cudaStreamNonBlocking);
        cudaEventCreateWithFlags(&evRoot, cudaEventDisableTiming);
        cudaEventCreateWithFlags(&evX1,   cudaEventDisableTiming);
        cudaEventCreateWithFlags(&evWt,   cudaEventDisableTiming);
        cudaEventCreateWithFlags(&evW,    cudaEventDisableTiming);
        cudaEventCreateWithFlags(&evF,    cudaEventDisableTiming);
        cudaEventCreateWithFlags(&evKm,   cudaEventDisableTiming);
        cudaEventCreateWithFlags(&evA,    cudaEventDisableTiming);
        cudaEventCreateWithFlags(&evSeg,  cudaEventDisableTiming);
    }

    const int SMC  = 3 * 49152;   // conv: S=3, 48KB stages = 147456
    const int SMB0 = 2 * 32768;   // small GEMMs
    cudaFuncSetAttribute(conv_gemm<3>, cudaFuncAttributeMaxDynamicSharedMemorySize, SMC);
    cudaFuncSetAttribute(mm_gemm<5, 2>, cudaFuncAttributeMaxDynamicSharedMemorySize, SMB0);
    cudaFuncSetAttribute(mm_gemm<2, 2>, cudaFuncAttributeMaxDynamicSharedMemorySize, SMB0);
    cudaFuncSetAttribute(mm_gemm<3, 2>, cudaFuncAttributeMaxDynamicSharedMemorySize, SMB0);

    // fork points
    cudaEventRecord(evRoot, 0);
    cudaStreamWaitEvent(s1, evRoot, 0);
    cudaStreamWaitEvent(s2, evRoot, 0);

    // #1: x half0 (main); #2: x half1 (s2); #3: conv weights (s1)
    conv_x_k<<<32768, 256>>>((const float4*)x, (__half2*)xh);
    conv_x_k<<<32768, 256, 0, s2>>>((const float4*)x + 8388608, (__half2*)(xh + 33554432));
    cudaEventRecord(evX1, s2);
    splitw_conv_k<<<(L_ * KCONV) / 256, 256, 0, s1>>>(tsn_w, wt);
    cudaEventRecord(evWt, s1);

    // #4: conv GEMM, single launch, 128 CTAs  [PROFILED]
    cudaStreamWaitEvent(0, evWt, 0);
    cudaStreamWaitEvent(0, evX1, 0);
    conv_gemm<3><<<128, 256, SMC>>>(xh, wt, tsn_b, feat, fhi);
    cudaEventRecord(evF, 0);

    // weight repacks on s1 (overlap conv)
    splitw_pair_k<<<512, 256, 0, s1>>>(aV_w, aU_w, bw);
    splitw_gen_k<<<256, 256, 0, s1>>>(cs_w0, 257, 65536, bw + 131072);
    splitw_gen_k<<<128, 256, 0, s1>>>(cs_w1, 256, 32768, bw + 196608);
    cudaEventRecord(evW, s1);

    // kmeans on s2 after feat
    cudaStreamWaitEvent(s2, evF, 0);
    kmeans_assign_k<<<B_, 512, 0, s2>>>(feat, oAssign, kmask);
    cudaEventRecord(evKm, s2);

    // main chain: fused aVU+gated -> Amat
    cudaStreamWaitEvent(0, evW, 0);
    mm_gemm<5, 2><<<dim3(4, 128), 256, SMB0>>>(fhi, 256, bw, 256,
                                               aV_b, aU_b, gate_w,
                                               part, nullptr, 512, 256);
    gatedfin_k<<<M_ / 256, 256>>>(part, gate_b, Amat);
    cudaEventRecord(evA, 0);

    // seg chain on s1
    cudaStreamWaitEvent(s1, evA, 0);
    mm_gemm<2, 2><<<dim3(2, 128), 256, SMB0, s1>>>(fhi, 256, bw + 131072, 256,
                                                   cs_b0, Amat, cs_w0 + 256,
                                                   nullptr, h0hi, 256, 256);
    mm_gemm<3, 2><<<dim3(1, 128), 256, SMB0, s1>>>(h0hi, 256, bw + 196608, 256,
                                                   cs_b1, nullptr, nullptr,
                                                   h1, nullptr, 128, 256);
    segtail_kernel<<<M_ / 8, 256, 0, s1>>>(h1, cs_w2, cs_b2, cs_w3, cs_b3, oSeg);
    cudaEventRecord(evSeg, s1);

    // bag chain on main stream
    softbag_kernel<<<B_, 256>>>(Amat, feat, bag, oAt);
    bagclf_kernel<<<B_ / 8, 256>>>(bag, cb_w0, cb_b0, cb_w1, cb_b1,
                                   cb_w2, cb_b2, cb_w3, cb_b3, oOut);

    // join
    cudaStreamWaitEvent(0, evSeg, 0);
    cudaStreamWaitEvent(0, evKm, 0);
    out2_k<<<B_ / 8, 256>>>(kmask, oSeg, oOut);
}